// round 5
// baseline (speedup 1.0000x reference)
#include <cuda_runtime.h>
#include <cstdint>

#define B_ 4
#define S_ 1024
#define E_ 512
#define C_ 256
#define H_ 1024
#define V_ 32000
#define G_ 128   // CTAs in the persistent sequential kernel (<= SM count -> co-resident)

// ---------------- scratch (device globals: no allocations allowed) ----------------
__device__ float g_X [S_ * B_ * E_];   // [r=t*B+b][E]   8 MB
__device__ float g_Z [S_ * B_ * H_];   // [r][H] = X@W0x^T + b0   16 MB
__device__ float g_H1[S_ * B_ * H_];   // [r][H] all h1 states    16 MB
__device__ float g_h0 [H_ * B_];       // current h0, layout [k][b]
__device__ float g_h1 [H_ * B_];       // current h1, layout [k][b]
__device__ float g_ctx[C_ * B_];       // current ctx, layout [k][b]
__device__ unsigned g_ctr;             // global barrier counter

__global__ void reset_kernel() { g_ctr = 0u; }

// ---------------- embedding: X[r][e] = tok_emb[ids[b][t]][e] + pos_emb[t][e] ----------------
__global__ void embed_kernel(const int* __restrict__ ids,
                             const float* __restrict__ tok,
                             const float* __restrict__ pos)
{
    int r = blockIdx.x;            // r = t*B + b
    int t = r >> 2, b = r & 3;
    int id = ids[b * S_ + t];
    const float4* tp = (const float4*)(tok + (size_t)id * E_);
    const float4* pp = (const float4*)(pos + (size_t)t * E_);
    float4* xp = (float4*)(g_X + (size_t)r * E_);
    int e = threadIdx.x;           // blockDim = 128, E_/4 = 128
    float4 a = tp[e], p = pp[e];
    xp[e] = make_float4(a.x + p.x, a.y + p.y, a.z + p.z, a.w + p.w);
}

// ---------------- generic fp32 GEMM: C[M,N] = A[M,K] @ Bw[N,K]^T + bias[N] ----------------
// A row-major (lda), Bw row-major (ldb) — both K-contiguous ("TN" dot-product form).
// scatter=1: row m -> (b=m&3, t=m>>2) -> C[(b*S_+t)*Nout + n]  (logits layout [B,S,V])
#define BM 128
#define BN 128
#define BK 16
#define PADW 132

__global__ __launch_bounds__(256, 2) void sgemm_tn(
    const float* __restrict__ A, int lda,
    const float* __restrict__ Bw, int ldb,
    const float* __restrict__ bias,
    float* __restrict__ Cout,
    int K, int scatter, int Nout)
{
    __shared__ float As[BK][PADW];
    __shared__ float Bs[BK][PADW];

    int tid = threadIdx.x;
    int tx = tid & 15, ty = tid >> 4;
    int bm = blockIdx.y * BM, bn = blockIdx.x * BN;

    float acc[8][8];
#pragma unroll
    for (int i = 0; i < 8; i++)
#pragma unroll
        for (int j = 0; j < 8; j++) acc[i][j] = 0.f;

    int lrow = tid >> 2;            // 0..63
    int lkq  = (tid & 3) * 4;       // 0,4,8,12

    for (int kt = 0; kt < K; kt += BK) {
#pragma unroll
        for (int h = 0; h < 2; h++) {
            int row = lrow + h * 64;
            float4 va = *(const float4*)(A  + (size_t)(bm + row) * lda + kt + lkq);
            As[lkq + 0][row] = va.x; As[lkq + 1][row] = va.y;
            As[lkq + 2][row] = va.z; As[lkq + 3][row] = va.w;
            float4 vb = *(const float4*)(Bw + (size_t)(bn + row) * ldb + kt + lkq);
            Bs[lkq + 0][row] = vb.x; Bs[lkq + 1][row] = vb.y;
            Bs[lkq + 2][row] = vb.z; Bs[lkq + 3][row] = vb.w;
        }
        __syncthreads();
#pragma unroll
        for (int kk = 0; kk < BK; kk++) {
            float a[8], b[8];
            *(float4*)(a)     = *(const float4*)&As[kk][ty * 8];
            *(float4*)(a + 4) = *(const float4*)&As[kk][ty * 8 + 4];
            *(float4*)(b)     = *(const float4*)&Bs[kk][tx * 8];
            *(float4*)(b + 4) = *(const float4*)&Bs[kk][tx * 8 + 4];
#pragma unroll
            for (int i = 0; i < 8; i++)
#pragma unroll
                for (int j = 0; j < 8; j++)
                    acc[i][j] += a[i] * b[j];
        }
        __syncthreads();
    }

    float bv[8];
#pragma unroll
    for (int j = 0; j < 8; j++) bv[j] = bias[bn + tx * 8 + j];

#pragma unroll
    for (int i = 0; i < 8; i++) {
        int m = bm + ty * 8 + i;
        size_t base;
        if (scatter) {
            int bb = m & 3, tt = m >> 2;
            base = ((size_t)bb * S_ + tt) * (size_t)Nout;
        } else {
            base = (size_t)m * (size_t)Nout;
        }
        float4 o0, o1;
        o0.x = acc[i][0] + bv[0]; o0.y = acc[i][1] + bv[1];
        o0.z = acc[i][2] + bv[2]; o0.w = acc[i][3] + bv[3];
        o1.x = acc[i][4] + bv[4]; o1.y = acc[i][5] + bv[5];
        o1.z = acc[i][6] + bv[6]; o1.w = acc[i][7] + bv[7];
        *(float4*)(Cout + base + bn + tx * 8)     = o0;
        *(float4*)(Cout + base + bn + tx * 8 + 4) = o1;
    }
}

// ---------------- global barrier (monotonic counter, reset per launch) ----------------
__device__ __forceinline__ void gbar(unsigned target)
{
    __threadfence();
    __syncthreads();
    if (threadIdx.x == 0) {
        asm volatile("red.release.gpu.add.u32 [%0], %1;" :: "l"(&g_ctr), "r"(1u) : "memory");
        unsigned v;
        do {
            asm volatile("ld.acquire.gpu.u32 %0, [%1];" : "=r"(v) : "l"(&g_ctr) : "memory");
        } while (v < target);
    }
    __syncthreads();
}

__device__ __forceinline__ float wsum(float v)
{
    v += __shfl_down_sync(0xffffffffu, v, 16);
    v += __shfl_down_sync(0xffffffffu, v, 8);
    v += __shfl_down_sync(0xffffffffu, v, 4);
    v += __shfl_down_sync(0xffffffffu, v, 2);
    v += __shfl_down_sync(0xffffffffu, v, 1);
    return v;
}

// ---------------- persistent sequential recurrence ----------------
// 128 CTAs x 256 threads. CTA c owns:
//   h0/h1 rows [8c, 8c+8)  (W0c slice 8x256, W1 slice 8x1024 in SMEM)
//   ctx rows   [2c, 2c+2)  (Wc slice 2x1024 in SMEM)
// Per step: stage1 h0 = relu(Z[t] + W0c@ctx) | bar | stage2 h1 = relu(W1@h0+b1) | bar |
//           stage3 traj<-ctx; ctx += Wc@h1 + bc | bar
__global__ __launch_bounds__(256) void recur_kernel(
    const float* __restrict__ W0, const float* __restrict__ W1,
    const float* __restrict__ b1, const float* __restrict__ Wc,
    const float* __restrict__ bc, float* __restrict__ traj_out)
{
    __shared__ float sW0c[8][256];   //  8 KB
    __shared__ float sW1 [8][1024];  // 32 KB
    __shared__ float sWc [2][1024];  //  8 KB  -> 48 KB total (static limit OK)

    int c = blockIdx.x, tid = threadIdx.x;
    int w = tid >> 5, lane = tid & 31;

    // stage weights into SMEM once
    for (int i = tid; i < 512; i += 256) {            // W0c: 8 rows x 64 f4
        int j = i >> 6, kq = (i & 63) * 4;
        *(float4*)&sW0c[j][kq] =
            *(const float4*)(W0 + (size_t)(c * 8 + j) * (E_ + C_) + E_ + kq);
    }
    for (int i = tid; i < 2048; i += 256) {           // W1: 8 rows x 256 f4
        int j = i >> 8, kq = (i & 255) * 4;
        *(float4*)&sW1[j][kq] = *(const float4*)(W1 + (size_t)(c * 8 + j) * H_ + kq);
    }
    for (int i = tid; i < 512; i += 256) {            // Wc: 2 rows x 256 f4
        int j = i >> 8, kq = (i & 255) * 4;
        *(float4*)&sWc[j][kq] = *(const float4*)(Wc + (size_t)(c * 2 + j) * H_ + kq);
    }

    int h_row = c * 8 + w;
    float rb1 = b1[h_row];
    int c3row = c * 2 + (w >> 2);    // stage3: warp w -> (row, batch)
    int c3b   = w & 3;
    float rbc = bc[c3row];
    __syncthreads();

    unsigned bar = 0;
    for (int t = 0; t < S_; t++) {
        // ---- stage 1: h0 ----
        {
            float z0 = g_Z[(size_t)(t * 4 + 0) * H_ + h_row];
            float z1 = g_Z[(size_t)(t * 4 + 1) * H_ + h_row];
            float z2 = g_Z[(size_t)(t * 4 + 2) * H_ + h_row];
            float z3 = g_Z[(size_t)(t * 4 + 3) * H_ + h_row];
            float a0 = 0.f, a1 = 0.f, a2 = 0.f, a3 = 0.f;
            if (t) {
#pragma unroll
                for (int i = 0; i < 8; i++) {
                    int k = lane + i * 32;
                    float wv = sW0c[w][k];
                    float4 cv = *(const float4*)(g_ctx + k * 4);
                    a0 += wv * cv.x; a1 += wv * cv.y; a2 += wv * cv.z; a3 += wv * cv.w;
                }
                a0 = wsum(a0); a1 = wsum(a1); a2 = wsum(a2); a3 = wsum(a3);
            }
            if (lane == 0) {
                float4 h;
                h.x = fmaxf(z0 + a0, 0.f); h.y = fmaxf(z1 + a1, 0.f);
                h.z = fmaxf(z2 + a2, 0.f); h.w = fmaxf(z3 + a3, 0.f);
                *(float4*)(g_h0 + h_row * 4) = h;
            }
        }
        gbar(++bar * G_);

        // ---- stage 2: h1 ----
        {
            float a0 = 0.f, a1 = 0.f, a2 = 0.f, a3 = 0.f;
#pragma unroll 8
            for (int i = 0; i < 32; i++) {
                int k = lane + i * 32;
                float wv = sW1[w][k];
                float4 hv = *(const float4*)(g_h0 + k * 4);
                a0 += wv * hv.x; a1 += wv * hv.y; a2 += wv * hv.z; a3 += wv * hv.w;
            }
            a0 = wsum(a0); a1 = wsum(a1); a2 = wsum(a2); a3 = wsum(a3);
            if (lane == 0) {
                float4 h;
                h.x = fmaxf(a0 + rb1, 0.f); h.y = fmaxf(a1 + rb1, 0.f);
                h.z = fmaxf(a2 + rb1, 0.f); h.w = fmaxf(a3 + rb1, 0.f);
                *(float4*)(g_h1 + h_row * 4) = h;
                g_H1[(size_t)(t * 4 + 0) * H_ + h_row] = h.x;
                g_H1[(size_t)(t * 4 + 1) * H_ + h_row] = h.y;
                g_H1[(size_t)(t * 4 + 2) * H_ + h_row] = h.z;
                g_H1[(size_t)(t * 4 + 3) * H_ + h_row] = h.w;
            }
        }
        gbar(++bar * G_);

        // ---- stage 3: traj + ctx update ----
        {
            float acc = 0.f;
#pragma unroll 8
            for (int i = 0; i < 32; i++) {
                int k = lane + i * 32;
                acc += sWc[w >> 2][k] * g_h1[k * 4 + c3b];
            }
            acc = wsum(acc);
            if (lane == 0) {
                float oldv = t ? g_ctx[c3row * 4 + c3b] : 0.f;
                traj_out[((size_t)c3b * S_ + t) * C_ + c3row] = oldv;
                g_ctx[c3row * 4 + c3b] = oldv + acc + rbc;
            }
        }
        gbar(++bar * G_);
    }
}

// ---------------- launch ----------------
extern "C" void kernel_launch(void* const* d_in, const int* in_sizes, int n_in,
                              void* d_out, int out_size)
{
    const int*   ids  = (const int*)  d_in[0];
    const float* tok  = (const float*)d_in[1];
    const float* pos  = (const float*)d_in[2];
    const float* W0   = (const float*)d_in[3];
    const float* b0   = (const float*)d_in[4];
    const float* W1   = (const float*)d_in[5];
    const float* b1   = (const float*)d_in[6];
    const float* Wout = (const float*)d_in[7];
    const float* bout = (const float*)d_in[8];
    const float* Wc   = (const float*)d_in[9];
    const float* bc   = (const float*)d_in[10];

    float* out  = (float*)d_out;                         // logits [B,S,V]
    float* traj = out + (size_t)B_ * S_ * V_;            // traj   [B,S,C]

    float *pX, *pZ, *pH1;
    cudaGetSymbolAddress((void**)&pX,  g_X);
    cudaGetSymbolAddress((void**)&pZ,  g_Z);
    cudaGetSymbolAddress((void**)&pH1, g_H1);

    reset_kernel<<<1, 1>>>();
    embed_kernel<<<S_ * B_, 128>>>(ids, tok, pos);
    // Z = X @ W0x^T + b0   (M=4096, N=1024, K=512; W0 row stride = 768, x-part = cols [0,512))
    sgemm_tn<<<dim3(H_ / BN, (S_ * B_) / BM), 256>>>(pX, E_, W0, E_ + C_, b0, pZ, E_, 0, H_);
    // sequential recurrence -> g_H1, traj
    recur_kernel<<<G_, 256>>>(W0, W1, b1, Wc, bc, traj);
    // logits = H1 @ Wout^T + bout  (M=4096, N=32000, K=1024), scatter to [B,S,V]
    sgemm_tn<<<dim3(V_ / BN, (S_ * B_) / BM), 256>>>(pH1, H_, Wout, H_, bout, out, H_, 1, V_);
}

// round 6
// speedup vs baseline: 1.2589x; 1.2589x over previous
#include <cuda_runtime.h>
#include <cstdint>

#define B_ 4
#define S_ 1024
#define E_ 512
#define C_ 256
#define H_ 1024
#define V_ 32000
#define G_ 128   // CTAs in the persistent sequential kernel (co-resident)

// ---------------- scratch (device globals: no allocations allowed) ----------------
__device__ float g_X [S_ * B_ * E_];   // [r=t*B+b][E]
__device__ float g_Z [S_ * B_ * H_];   // [r][H] = X@W0x^T + b0
__device__ float g_H1[S_ * B_ * H_];   // [r][H] all h1 states
__device__ float g_h0 [H_ * B_];       // current h0, layout [k][b]
__device__ float g_h1 [H_ * B_];       // current h1, layout [k][b]
__device__ float g_ctx[C_ * B_];       // current ctx, layout [k][b]
__device__ unsigned g_ctr;             // global barrier counter

__global__ void reset_kernel() { g_ctr = 0u; }

// ---------------- embedding ----------------
__global__ void embed_kernel(const int* __restrict__ ids,
                             const float* __restrict__ tok,
                             const float* __restrict__ pos)
{
    int r = blockIdx.x;            // r = t*B + b
    int t = r >> 2, b = r & 3;
    int id = ids[b * S_ + t];
    const float4* tp = (const float4*)(tok + (size_t)id * E_);
    const float4* pp = (const float4*)(pos + (size_t)t * E_);
    float4* xp = (float4*)(g_X + (size_t)r * E_);
    int e = threadIdx.x;           // blockDim = 128, E_/4 = 128
    float4 a = tp[e], p = pp[e];
    xp[e] = make_float4(a.x + p.x, a.y + p.y, a.z + p.z, a.w + p.w);
}

// ---------------- fp32 SGEMM (used only for Z, K=512) ----------------
#define BM 128
#define BN 128
#define BK 16
#define PADW 132

__global__ __launch_bounds__(256, 2) void sgemm_tn(
    const float* __restrict__ A, int lda,
    const float* __restrict__ Bw, int ldb,
    const float* __restrict__ bias,
    float* __restrict__ Cout,
    int K, int Nout)
{
    __shared__ float As[BK][PADW];
    __shared__ float Bs[BK][PADW];

    int tid = threadIdx.x;
    int tx = tid & 15, ty = tid >> 4;
    int bm = blockIdx.y * BM, bn = blockIdx.x * BN;

    float acc[8][8];
#pragma unroll
    for (int i = 0; i < 8; i++)
#pragma unroll
        for (int j = 0; j < 8; j++) acc[i][j] = 0.f;

    int lrow = tid >> 2;
    int lkq  = (tid & 3) * 4;

    for (int kt = 0; kt < K; kt += BK) {
#pragma unroll
        for (int h = 0; h < 2; h++) {
            int row = lrow + h * 64;
            float4 va = *(const float4*)(A  + (size_t)(bm + row) * lda + kt + lkq);
            As[lkq + 0][row] = va.x; As[lkq + 1][row] = va.y;
            As[lkq + 2][row] = va.z; As[lkq + 3][row] = va.w;
            float4 vb = *(const float4*)(Bw + (size_t)(bn + row) * ldb + kt + lkq);
            Bs[lkq + 0][row] = vb.x; Bs[lkq + 1][row] = vb.y;
            Bs[lkq + 2][row] = vb.z; Bs[lkq + 3][row] = vb.w;
        }
        __syncthreads();
#pragma unroll
        for (int kk = 0; kk < BK; kk++) {
            float a[8], b[8];
            *(float4*)(a)     = *(const float4*)&As[kk][ty * 8];
            *(float4*)(a + 4) = *(const float4*)&As[kk][ty * 8 + 4];
            *(float4*)(b)     = *(const float4*)&Bs[kk][tx * 8];
            *(float4*)(b + 4) = *(const float4*)&Bs[kk][tx * 8 + 4];
#pragma unroll
            for (int i = 0; i < 8; i++)
#pragma unroll
                for (int j = 0; j < 8; j++)
                    acc[i][j] += a[i] * b[j];
        }
        __syncthreads();
    }

    float bv[8];
#pragma unroll
    for (int j = 0; j < 8; j++) bv[j] = bias[bn + tx * 8 + j];

#pragma unroll
    for (int i = 0; i < 8; i++) {
        int m = bm + ty * 8 + i;
        size_t base = (size_t)m * (size_t)Nout;
        float4 o0, o1;
        o0.x = acc[i][0] + bv[0]; o0.y = acc[i][1] + bv[1];
        o0.z = acc[i][2] + bv[2]; o0.w = acc[i][3] + bv[3];
        o1.x = acc[i][4] + bv[4]; o1.y = acc[i][5] + bv[5];
        o1.z = acc[i][6] + bv[6]; o1.w = acc[i][7] + bv[7];
        *(float4*)(Cout + base + bn + tx * 8)     = o0;
        *(float4*)(Cout + base + bn + tx * 8 + 4) = o1;
    }
}

// ---------------- tf32 tensor-core GEMM for logits ----------------
// C[m][n] = sum_k H1[m][k] * Wout[n][k] + bout[n], scattered to [B,S,V].
// M=4096, N=32000, K=1024.  Tiles 128x128x16, 8 warps (warp tile 32x64),
// mma.sync.m16n8k8.tf32. Both tiles staged [row][k] stride 20 (conflict-free).
#define TKS 20   // smem row stride in words (16 + 4 pad -> bank-conflict-free frags)

__device__ __forceinline__ uint32_t f2tf(float f)
{
    uint32_t r;
    asm("cvt.rna.tf32.f32 %0, %1;" : "=r"(r) : "f"(f));
    return r;
}

__global__ __launch_bounds__(256, 2) void mma_logits(
    const float* __restrict__ A,    // g_H1 [4096][1024]
    const float* __restrict__ Bw,   // Wout [32000][1024]
    const float* __restrict__ bias, // bout
    float* __restrict__ Cout)       // logits [B,S,V]
{
    __shared__ uint32_t As[128][TKS];
    __shared__ uint32_t Bs[128][TKS];

    int tid = threadIdx.x;
    int lane = tid & 31, wid = tid >> 5;
    int wm = (wid & 3) * 32;        // 4 warps along M
    int wn = (wid >> 2) * 64;       // 2 warps along N
    int g  = lane >> 2, tq = lane & 3;

    int bm = blockIdx.x * 128;      // x fastest -> wave shares B tiles, A stays in L2
    int bn = blockIdx.y * 128;

    int lrow = tid >> 1;            // 0..127
    int lkq  = (tid & 1) * 8;       // 0 or 8

    float c[2][8][4];
#pragma unroll
    for (int mt = 0; mt < 2; mt++)
#pragma unroll
        for (int nt = 0; nt < 8; nt++)
#pragma unroll
            for (int i = 0; i < 4; i++) c[mt][nt][i] = 0.f;

    const float* Aptr = A  + (size_t)(bm + lrow) * H_ + lkq;
    const float* Bptr = Bw + (size_t)(bn + lrow) * H_ + lkq;

    float4 pa0 = *(const float4*)(Aptr);
    float4 pa1 = *(const float4*)(Aptr + 4);
    float4 pb0 = *(const float4*)(Bptr);
    float4 pb1 = *(const float4*)(Bptr + 4);

    for (int kt = 0; kt < H_; kt += 16) {
        // stage current tile (fp32 -> tf32) as [row][k]
        *(uint4*)&As[lrow][lkq]     = make_uint4(f2tf(pa0.x), f2tf(pa0.y), f2tf(pa0.z), f2tf(pa0.w));
        *(uint4*)&As[lrow][lkq + 4] = make_uint4(f2tf(pa1.x), f2tf(pa1.y), f2tf(pa1.z), f2tf(pa1.w));
        *(uint4*)&Bs[lrow][lkq]     = make_uint4(f2tf(pb0.x), f2tf(pb0.y), f2tf(pb0.z), f2tf(pb0.w));
        *(uint4*)&Bs[lrow][lkq + 4] = make_uint4(f2tf(pb1.x), f2tf(pb1.y), f2tf(pb1.z), f2tf(pb1.w));
        __syncthreads();

        // prefetch next tile
        if (kt + 16 < H_) {
            pa0 = *(const float4*)(Aptr + kt + 16);
            pa1 = *(const float4*)(Aptr + kt + 20);
            pb0 = *(const float4*)(Bptr + kt + 16);
            pb1 = *(const float4*)(Bptr + kt + 20);
        }

#pragma unroll
        for (int ks = 0; ks < 2; ks++) {
            int kb = ks * 8;
            uint32_t a[2][4];
#pragma unroll
            for (int mt = 0; mt < 2; mt++) {
                int m = wm + mt * 16 + g;
                a[mt][0] = As[m][kb + tq];          // A[g][t]
                a[mt][1] = As[m + 8][kb + tq];      // A[g+8][t]
                a[mt][2] = As[m][kb + tq + 4];      // A[g][t+4]
                a[mt][3] = As[m + 8][kb + tq + 4];  // A[g+8][t+4]
            }
            uint32_t b[8][2];
#pragma unroll
            for (int nt = 0; nt < 8; nt++) {
                int n = wn + nt * 8 + g;
                b[nt][0] = Bs[n][kb + tq];          // B[t][g]
                b[nt][1] = Bs[n][kb + tq + 4];      // B[t+4][g]
            }
#pragma unroll
            for (int mt = 0; mt < 2; mt++)
#pragma unroll
                for (int nt = 0; nt < 8; nt++) {
                    asm volatile(
                        "mma.sync.aligned.m16n8k8.row.col.f32.tf32.tf32.f32 "
                        "{%0,%1,%2,%3}, {%4,%5,%6,%7}, {%8,%9}, {%0,%1,%2,%3};\n"
                        : "+f"(c[mt][nt][0]), "+f"(c[mt][nt][1]),
                          "+f"(c[mt][nt][2]), "+f"(c[mt][nt][3])
                        : "r"(a[mt][0]), "r"(a[mt][1]), "r"(a[mt][2]), "r"(a[mt][3]),
                          "r"(b[nt][0]), "r"(b[nt][1]));
                }
        }
        __syncthreads();
    }

    // epilogue: bias + scatter row m -> (b=m&3, t=m>>2) -> logits[b][t][:]
#pragma unroll
    for (int nt = 0; nt < 8; nt++) {
        int col = bn + wn + nt * 8 + tq * 2;
        float bv0 = bias[col], bv1 = bias[col + 1];
#pragma unroll
        for (int mt = 0; mt < 2; mt++) {
            int m0 = bm + wm + mt * 16 + g;
            {
                int bb = m0 & 3, tt = m0 >> 2;
                float2 o = make_float2(c[mt][nt][0] + bv0, c[mt][nt][1] + bv1);
                *(float2*)(Cout + ((size_t)bb * S_ + tt) * (size_t)V_ + col) = o;
            }
            {
                int m1 = m0 + 8;
                int bb = m1 & 3, tt = m1 >> 2;
                float2 o = make_float2(c[mt][nt][2] + bv0, c[mt][nt][3] + bv1);
                *(float2*)(Cout + ((size_t)bb * S_ + tt) * (size_t)V_ + col) = o;
            }
        }
    }
}

// ---------------- global barrier ----------------
__device__ __forceinline__ void gbar(unsigned target)
{
    __threadfence();
    __syncthreads();
    if (threadIdx.x == 0) {
        asm volatile("red.release.gpu.add.u32 [%0], %1;" :: "l"(&g_ctr), "r"(1u) : "memory");
        unsigned v;
        do {
            asm volatile("ld.acquire.gpu.u32 %0, [%1];" : "=r"(v) : "l"(&g_ctr) : "memory");
        } while (v < target);
    }
    __syncthreads();
}

__device__ __forceinline__ float wsum(float v)
{
    v += __shfl_down_sync(0xffffffffu, v, 16);
    v += __shfl_down_sync(0xffffffffu, v, 8);
    v += __shfl_down_sync(0xffffffffu, v, 4);
    v += __shfl_down_sync(0xffffffffu, v, 2);
    v += __shfl_down_sync(0xffffffffu, v, 1);
    return v;
}

// ---------------- persistent sequential recurrence ----------------
__global__ __launch_bounds__(256) void recur_kernel(
    const float* __restrict__ W0, const float* __restrict__ W1,
    const float* __restrict__ b1, const float* __restrict__ Wc,
    const float* __restrict__ bc, float* __restrict__ traj_out)
{
    __shared__ float sW0c[8][256];
    __shared__ float sW1 [8][1024];
    __shared__ float sWc [2][1024];

    int c = blockIdx.x, tid = threadIdx.x;
    int w = tid >> 5, lane = tid & 31;

    for (int i = tid; i < 512; i += 256) {
        int j = i >> 6, kq = (i & 63) * 4;
        *(float4*)&sW0c[j][kq] =
            *(const float4*)(W0 + (size_t)(c * 8 + j) * (E_ + C_) + E_ + kq);
    }
    for (int i = tid; i < 2048; i += 256) {
        int j = i >> 8, kq = (i & 255) * 4;
        *(float4*)&sW1[j][kq] = *(const float4*)(W1 + (size_t)(c * 8 + j) * H_ + kq);
    }
    for (int i = tid; i < 512; i += 256) {
        int j = i >> 8, kq = (i & 255) * 4;
        *(float4*)&sWc[j][kq] = *(const float4*)(Wc + (size_t)(c * 2 + j) * H_ + kq);
    }

    int h_row = c * 8 + w;
    float rb1 = b1[h_row];
    int c3row = c * 2 + (w >> 2);
    int c3b   = w & 3;
    float rbc = bc[c3row];
    __syncthreads();

    unsigned bar = 0;
    for (int t = 0; t < S_; t++) {
        // ---- stage 1: h0 ----
        {
            float z0 = g_Z[(size_t)(t * 4 + 0) * H_ + h_row];
            float z1 = g_Z[(size_t)(t * 4 + 1) * H_ + h_row];
            float z2 = g_Z[(size_t)(t * 4 + 2) * H_ + h_row];
            float z3 = g_Z[(size_t)(t * 4 + 3) * H_ + h_row];
            float a0 = 0.f, a1 = 0.f, a2 = 0.f, a3 = 0.f;
            if (t) {
#pragma unroll
                for (int i = 0; i < 8; i++) {
                    int k = lane + i * 32;
                    float wv = sW0c[w][k];
                    float4 cv = *(const float4*)(g_ctx + k * 4);
                    a0 += wv * cv.x; a1 += wv * cv.y; a2 += wv * cv.z; a3 += wv * cv.w;
                }
                a0 = wsum(a0); a1 = wsum(a1); a2 = wsum(a2); a3 = wsum(a3);
            }
            if (lane == 0) {
                float4 h;
                h.x = fmaxf(z0 + a0, 0.f); h.y = fmaxf(z1 + a1, 0.f);
                h.z = fmaxf(z2 + a2, 0.f); h.w = fmaxf(z3 + a3, 0.f);
                *(float4*)(g_h0 + h_row * 4) = h;
            }
        }
        gbar(++bar * G_);

        // ---- stage 2: h1 ----
        {
            float a0 = 0.f, a1 = 0.f, a2 = 0.f, a3 = 0.f;
#pragma unroll 8
            for (int i = 0; i < 32; i++) {
                int k = lane + i * 32;
                float wv = sW1[w][k];
                float4 hv = *(const float4*)(g_h0 + k * 4);
                a0 += wv * hv.x; a1 += wv * hv.y; a2 += wv * hv.z; a3 += wv * hv.w;
            }
            a0 = wsum(a0); a1 = wsum(a1); a2 = wsum(a2); a3 = wsum(a3);
            if (lane == 0) {
                float4 h;
                h.x = fmaxf(a0 + rb1, 0.f); h.y = fmaxf(a1 + rb1, 0.f);
                h.z = fmaxf(a2 + rb1, 0.f); h.w = fmaxf(a3 + rb1, 0.f);
                *(float4*)(g_h1 + h_row * 4) = h;
                g_H1[(size_t)(t * 4 + 0) * H_ + h_row] = h.x;
                g_H1[(size_t)(t * 4 + 1) * H_ + h_row] = h.y;
                g_H1[(size_t)(t * 4 + 2) * H_ + h_row] = h.z;
                g_H1[(size_t)(t * 4 + 3) * H_ + h_row] = h.w;
            }
        }
        gbar(++bar * G_);

        // ---- stage 3: traj + ctx update ----
        {
            float acc = 0.f;
#pragma unroll 8
            for (int i = 0; i < 32; i++) {
                int k = lane + i * 32;
                acc += sWc[w >> 2][k] * g_h1[k * 4 + c3b];
            }
            acc = wsum(acc);
            if (lane == 0) {
                float oldv = t ? g_ctx[c3row * 4 + c3b] : 0.f;
                traj_out[((size_t)c3b * S_ + t) * C_ + c3row] = oldv;
                g_ctx[c3row * 4 + c3b] = oldv + acc + rbc;
            }
        }
        gbar(++bar * G_);
    }
}

// ---------------- launch ----------------
extern "C" void kernel_launch(void* const* d_in, const int* in_sizes, int n_in,
                              void* d_out, int out_size)
{
    const int*   ids  = (const int*)  d_in[0];
    const float* tok  = (const float*)d_in[1];
    const float* pos  = (const float*)d_in[2];
    const float* W0   = (const float*)d_in[3];
    const float* b0   = (const float*)d_in[4];
    const float* W1   = (const float*)d_in[5];
    const float* b1   = (const float*)d_in[6];
    const float* Wout = (const float*)d_in[7];
    const float* bout = (const float*)d_in[8];
    const float* Wc   = (const float*)d_in[9];
    const float* bc   = (const float*)d_in[10];

    float* out  = (float*)d_out;                         // logits [B,S,V]
    float* traj = out + (size_t)B_ * S_ * V_;            // traj   [B,S,C]

    float *pX, *pZ, *pH1;
    cudaGetSymbolAddress((void**)&pX,  g_X);
    cudaGetSymbolAddress((void**)&pZ,  g_Z);
    cudaGetSymbolAddress((void**)&pH1, g_H1);

    reset_kernel<<<1, 1>>>();
    embed_kernel<<<S_ * B_, 128>>>(ids, tok, pos);
    // Z = X @ W0x^T + b0   (M=4096, N=1024, K=512)  -- fp32 (feeds the recurrence)
    sgemm_tn<<<dim3(H_ / BN, (S_ * B_) / BM), 256>>>(pX, E_, W0, E_ + C_, b0, pZ, E_, H_);
    // sequential recurrence -> g_H1, traj (fp32)
    recur_kernel<<<G_, 256>>>(W0, W1, b1, Wc, bc, traj);
    // logits = H1 @ Wout^T + bout  (tf32 tensor cores), scatter to [B,S,V]
    mma_logits<<<dim3((S_ * B_) / 128, V_ / 128), 256>>>(pH1, Wout, bout, out);
}

// round 10
// speedup vs baseline: 1.4960x; 1.1883x over previous
#include <cuda_runtime.h>
#include <cstdint>

#define B_ 4
#define S_ 1024
#define E_ 512
#define C_ 256
#define H_ 1024
#define V_ 32000
#define GR 64     // CTAs in persistent recurrence

// ---------------- scratch device globals ----------------
__device__ float g_X [S_ * B_ * E_];    // embeddings [r=t*4+b][E]
__device__ float g_Z [S_ * B_ * H_];    // X@W0x^T + b0
__device__ float g_H1[S_ * B_ * H_];    // exact h1 [r][H]   (traj prefix)
__device__ float g_Hr[S_ * B_ * H_];    // tf32-rounded h1   (GEMM A operand)
__device__ float g_PS[S_ * B_ * H_];    // exclusive prefix sums of h1
__device__ float g_Wr[(size_t)V_ * H_]; // tf32-rounded Wout
__device__ float g_M [H_ * H_];         // W0c @ Wc
__device__ float g_v [H_];              // W0c @ bc
__device__ float g_u  [H_ * B_];        // u state [k][b]
__device__ float g_h1s[H_ * B_];        // current h1 [k][b]
__device__ unsigned g_ctr;

__device__ __forceinline__ uint32_t f2tf(float f)
{
    uint32_t r;
    asm("cvt.rna.tf32.f32 %0, %1;" : "=r"(r) : "f"(f));
    return r;
}

__global__ void reset_kernel()
{
    int i = blockIdx.x * blockDim.x + threadIdx.x;
    if (i < H_ * B_) g_u[i] = 0.f;
    if (i == 0) g_ctr = 0u;
}

// ---------------- embedding ----------------
__global__ void embed_kernel(const int* __restrict__ ids,
                             const float* __restrict__ tok,
                             const float* __restrict__ pos)
{
    int r = blockIdx.x;            // r = t*4 + b
    int t = r >> 2, b = r & 3;
    int id = ids[b * S_ + t];
    const float4* tp = (const float4*)(tok + (size_t)id * E_);
    const float4* pp = (const float4*)(pos + (size_t)t * E_);
    float4* xp = (float4*)(g_X + (size_t)r * E_);
    int e = threadIdx.x;
    float4 a = tp[e], p = pp[e];
    xp[e] = make_float4(a.x + p.x, a.y + p.y, a.z + p.z, a.w + p.w);
}

// ---------------- M = W0c @ Wc  and  v = W0c @ bc ----------------
__global__ void mcomp_kernel(const float* __restrict__ W0,
                             const float* __restrict__ Wc)
{
    int j = blockIdx.x * 256 + threadIdx.x;   // 0..1023
    int i = blockIdx.y;                       // 0..1023
    const float* w0r = W0 + (size_t)i * (E_ + C_) + E_;
    float acc = 0.f;
#pragma unroll 4
    for (int c = 0; c < C_; c++)
        acc += w0r[c] * Wc[(size_t)c * H_ + j];
    g_M[(size_t)i * H_ + j] = acc;
}

__global__ void vcomp_kernel(const float* __restrict__ W0,
                             const float* __restrict__ bc)
{
    int i = blockIdx.x * 256 + threadIdx.x;
    if (i >= H_) return;
    const float* w0r = W0 + (size_t)i * (E_ + C_) + E_;
    float acc = 0.f;
#pragma unroll 4
    for (int c = 0; c < C_; c++) acc += w0r[c] * bc[c];
    g_v[i] = acc;
}

// ---------------- round Wout to tf32 (rna) ----------------
__global__ void roundw_kernel(const float* __restrict__ src, int n4)
{
    int i = blockIdx.x * blockDim.x + threadIdx.x;
    int stride = gridDim.x * blockDim.x;
    for (; i < n4; i += stride) {
        float4 vv = ((const float4*)src)[i];
        uint4 o = make_uint4(f2tf(vv.x), f2tf(vv.y), f2tf(vv.z), f2tf(vv.w));
        ((uint4*)g_Wr)[i] = o;
    }
}

// ---------------- fp32 SGEMM: C = A[M,K] @ Bw[N,K]^T + bias ----------------
// mode 0: plain row-major out.  mode 2: traj scatter (b=m&3,t=m>>2), bias*t.
#define BM 128
#define BN 128
#define BK 16
#define PADW 132

__global__ __launch_bounds__(256, 2) void sgemm_tn(
    const float* __restrict__ A, int lda,
    const float* __restrict__ Bw, int ldb,
    const float* __restrict__ bias,
    float* __restrict__ Cout,
    int K, int Nout, int mode)
{
    __shared__ float As[BK][PADW];
    __shared__ float Bs[BK][PADW];

    int tid = threadIdx.x;
    int tx = tid & 15, ty = tid >> 4;
    int bm = blockIdx.y * BM, bn = blockIdx.x * BN;

    float acc[8][8];
#pragma unroll
    for (int i = 0; i < 8; i++)
#pragma unroll
        for (int j = 0; j < 8; j++) acc[i][j] = 0.f;

    int lrow = tid >> 2;
    int lkq  = (tid & 3) * 4;

    for (int kt = 0; kt < K; kt += BK) {
#pragma unroll
        for (int h = 0; h < 2; h++) {
            int row = lrow + h * 64;
            float4 va = *(const float4*)(A  + (size_t)(bm + row) * lda + kt + lkq);
            As[lkq + 0][row] = va.x; As[lkq + 1][row] = va.y;
            As[lkq + 2][row] = va.z; As[lkq + 3][row] = va.w;
            float4 vb = *(const float4*)(Bw + (size_t)(bn + row) * ldb + kt + lkq);
            Bs[lkq + 0][row] = vb.x; Bs[lkq + 1][row] = vb.y;
            Bs[lkq + 2][row] = vb.z; Bs[lkq + 3][row] = vb.w;
        }
        __syncthreads();
#pragma unroll
        for (int kk = 0; kk < BK; kk++) {
            float a[8], b[8];
            *(float4*)(a)     = *(const float4*)&As[kk][ty * 8];
            *(float4*)(a + 4) = *(const float4*)&As[kk][ty * 8 + 4];
            *(float4*)(b)     = *(const float4*)&Bs[kk][tx * 8];
            *(float4*)(b + 4) = *(const float4*)&Bs[kk][tx * 8 + 4];
#pragma unroll
            for (int i = 0; i < 8; i++)
#pragma unroll
                for (int j = 0; j < 8; j++)
                    acc[i][j] += a[i] * b[j];
        }
        __syncthreads();
    }

    float bv[8];
#pragma unroll
    for (int j = 0; j < 8; j++) bv[j] = bias[bn + tx * 8 + j];

#pragma unroll
    for (int i = 0; i < 8; i++) {
        int m = bm + ty * 8 + i;
        size_t base;
        float bsc = 1.f;
        if (mode == 2) {
            int bb = m & 3, tt = m >> 2;
            base = ((size_t)bb * S_ + tt) * (size_t)Nout;
            bsc = (float)tt;
        } else {
            base = (size_t)m * (size_t)Nout;
        }
        float4 o0, o1;
        o0.x = acc[i][0] + bv[0] * bsc; o0.y = acc[i][1] + bv[1] * bsc;
        o0.z = acc[i][2] + bv[2] * bsc; o0.w = acc[i][3] + bv[3] * bsc;
        o1.x = acc[i][4] + bv[4] * bsc; o1.y = acc[i][5] + bv[5] * bsc;
        o1.z = acc[i][6] + bv[6] * bsc; o1.w = acc[i][7] + bv[7] * bsc;
        *(float4*)(Cout + base + bn + tx * 8)     = o0;
        *(float4*)(Cout + base + bn + tx * 8 + 4) = o1;
    }
}

// ---------------- global barrier ----------------
__device__ __forceinline__ void gbar(unsigned target)
{
    __threadfence();
    __syncthreads();
    if (threadIdx.x == 0) {
        asm volatile("red.release.gpu.add.u32 [%0], %1;" :: "l"(&g_ctr), "r"(1u) : "memory");
        unsigned v;
        do {
            asm volatile("ld.acquire.gpu.u32 %0, [%1];" : "=r"(v) : "l"(&g_ctr) : "memory");
        } while (v < target);
    }
    __syncthreads();
}

__device__ __forceinline__ float wsum(float v)
{
    v += __shfl_down_sync(0xffffffffu, v, 16);
    v += __shfl_down_sync(0xffffffffu, v, 8);
    v += __shfl_down_sync(0xffffffffu, v, 4);
    v += __shfl_down_sync(0xffffffffu, v, 2);
    v += __shfl_down_sync(0xffffffffu, v, 1);
    return v;
}

// ---------------- persistent u-space recurrence ----------------
// 64 CTAs x 512 threads.  CTA c owns h-rows [16c,16c+16).
// Per step: all CTAs recompute full h0 = relu(Z_t + u) locally (no barrier),
//   phase A: h1[r] = relu(W1[r]·h0 + b1)          | gbar
//   phase B: u[r] += M[r]·h1 + v[r]               | gbar
// dyn smem: sW1[16][1024] | sM[16][1024] | sh0[1024*4] | sh1[1024*4]
__global__ __launch_bounds__(512, 1) void recur2(
    const float* __restrict__ W1, const float* __restrict__ b1)
{
    extern __shared__ float smf[];
    float* sW1 = smf;                  // 16*1024
    float* sM  = smf + 16 * 1024;      // 16*1024
    float* sh0 = smf + 32 * 1024;      // 1024*4
    float* sh1 = smf + 36 * 1024;      // 1024*4

    int c = blockIdx.x, tid = threadIdx.x;
    int w = tid >> 5, lane = tid & 31;
    int rowbase = c * 16;
    int r = rowbase + w;               // this warp's global h-row

    for (int i = tid; i < 16 * 256; i += 512) {      // 16 rows x 256 float4
        int j = i >> 8, kq = (i & 255) * 4;
        *(float4*)&sW1[j * 1024 + kq] = *(const float4*)(W1 + (size_t)(rowbase + j) * H_ + kq);
        *(float4*)&sM [j * 1024 + kq] = *(const float4*)(g_M + (size_t)(rowbase + j) * H_ + kq);
    }
    float rb1 = b1[r];
    float rv  = g_v[r];
    __syncthreads();

    unsigned bar = 0;
    for (int t = 0; t < S_; t++) {
        int t4 = t * 4;
        // ---- stage full h0 = relu(Z_t + u) into smem ----
#pragma unroll
        for (int h = 0; h < 2; h++) {
            int k = tid + h * 512;
            float4 uv = *(const float4*)(g_u + k * 4);
            float z0 = g_Z[(size_t)(t4 + 0) * H_ + k];
            float z1 = g_Z[(size_t)(t4 + 1) * H_ + k];
            float z2 = g_Z[(size_t)(t4 + 2) * H_ + k];
            float z3 = g_Z[(size_t)(t4 + 3) * H_ + k];
            float4 h0;
            h0.x = fmaxf(z0 + uv.x, 0.f); h0.y = fmaxf(z1 + uv.y, 0.f);
            h0.z = fmaxf(z2 + uv.z, 0.f); h0.w = fmaxf(z3 + uv.w, 0.f);
            *(float4*)&sh0[k * 4] = h0;
        }
        __syncthreads();

        // ---- phase A: h1[r] = relu(W1[r]·h0 + b1) ----
        {
            float a0 = 0.f, a1 = 0.f, a2 = 0.f, a3 = 0.f;
            const float* wr = sW1 + w * 1024;
#pragma unroll 8
            for (int i = 0; i < 32; i++) {
                int k = lane + i * 32;
                float wv = wr[k];
                float4 hv = *(const float4*)&sh0[k * 4];
                a0 += wv * hv.x; a1 += wv * hv.y; a2 += wv * hv.z; a3 += wv * hv.w;
            }
            a0 = wsum(a0); a1 = wsum(a1); a2 = wsum(a2); a3 = wsum(a3);
            if (lane == 0) {
                float4 h;
                h.x = fmaxf(a0 + rb1, 0.f); h.y = fmaxf(a1 + rb1, 0.f);
                h.z = fmaxf(a2 + rb1, 0.f); h.w = fmaxf(a3 + rb1, 0.f);
                *(float4*)(g_h1s + r * 4) = h;
                g_H1[(size_t)(t4 + 0) * H_ + r] = h.x;
                g_H1[(size_t)(t4 + 1) * H_ + r] = h.y;
                g_H1[(size_t)(t4 + 2) * H_ + r] = h.z;
                g_H1[(size_t)(t4 + 3) * H_ + r] = h.w;
                g_Hr[(size_t)(t4 + 0) * H_ + r] = __uint_as_float(f2tf(h.x));
                g_Hr[(size_t)(t4 + 1) * H_ + r] = __uint_as_float(f2tf(h.y));
                g_Hr[(size_t)(t4 + 2) * H_ + r] = __uint_as_float(f2tf(h.z));
                g_Hr[(size_t)(t4 + 3) * H_ + r] = __uint_as_float(f2tf(h.w));
            }
        }
        gbar(++bar * GR);

        // ---- stage full h1 into smem ----
#pragma unroll
        for (int h = 0; h < 2; h++) {
            int k = tid + h * 512;
            *(float4*)&sh1[k * 4] = *(const float4*)(g_h1s + k * 4);
        }
        __syncthreads();

        // ---- phase B: u[r] += M[r]·h1 + v[r] ----
        {
            float a0 = 0.f, a1 = 0.f, a2 = 0.f, a3 = 0.f;
            const float* mr = sM + w * 1024;
#pragma unroll 8
            for (int i = 0; i < 32; i++) {
                int k = lane + i * 32;
                float wv = mr[k];
                float4 hv = *(const float4*)&sh1[k * 4];
                a0 += wv * hv.x; a1 += wv * hv.y; a2 += wv * hv.z; a3 += wv * hv.w;
            }
            a0 = wsum(a0); a1 = wsum(a1); a2 = wsum(a2); a3 = wsum(a3);
            if (lane == 0) {
                float4 u = *(const float4*)(g_u + r * 4);
                u.x += a0 + rv; u.y += a1 + rv; u.z += a2 + rv; u.w += a3 + rv;
                *(float4*)(g_u + r * 4) = u;
            }
        }
        gbar(++bar * GR);
    }
}

// ---------------- exclusive prefix sums of h1 over t ----------------
__global__ void ps_kernel()
{
    int idx = blockIdx.x * 256 + threadIdx.x;  // 0..4095
    int k = idx & 1023, b = idx >> 10;
    float acc = 0.f;
    for (int t = 0; t < S_; t += 4) {
        float x0 = g_H1[(size_t)((t + 0) * 4 + b) * H_ + k];
        float x1 = g_H1[(size_t)((t + 1) * 4 + b) * H_ + k];
        float x2 = g_H1[(size_t)((t + 2) * 4 + b) * H_ + k];
        float x3 = g_H1[(size_t)((t + 3) * 4 + b) * H_ + k];
        g_PS[(size_t)((t + 0) * 4 + b) * H_ + k] = acc; acc += x0;
        g_PS[(size_t)((t + 1) * 4 + b) * H_ + k] = acc; acc += x1;
        g_PS[(size_t)((t + 2) * 4 + b) * H_ + k] = acc; acc += x2;
        g_PS[(size_t)((t + 3) * 4 + b) * H_ + k] = acc; acc += x3;
    }
}

// ================ tf32 mma.sync logits GEMM, 3-stage cp.async ================
// C[m][n] = sum_k Hr[m][k]*Wr[n][k] + bout[n], scatter row m -> [b=m&3][t=m>>2].
// Tiles 128x128x16, 8 warps (warp tile 32x64), operands pre-rounded to tf32.
#define TKS 20                         // smem row stride words (conflict-free frags)
#define STG_W (128 * TKS)              // words per operand per stage
#define NST 3

__device__ __forceinline__ void cpa16(uint32_t dst, const float* src)
{
    asm volatile("cp.async.cg.shared.global [%0], [%1], 16;" :: "r"(dst), "l"(src));
}

static __device__ __forceinline__ uint32_t smem_u32(const void* p)
{
    uint32_t a;
    asm("{ .reg .u64 t; cvta.to.shared.u64 t, %1; cvt.u32.u64 %0, t; }" : "=r"(a) : "l"(p));
    return a;
}

__global__ __launch_bounds__(256, 2) void mma_logits(
    const float* __restrict__ A,    // g_Hr [4096][1024]
    const float* __restrict__ Bw,   // g_Wr [32000][1024]
    const float* __restrict__ bias,
    float* __restrict__ Cout)
{
    extern __shared__ float sm[];
    int tid = threadIdx.x;
    int lane = tid & 31, wid = tid >> 5;
    int wm = (wid & 3) * 32;
    int wn = (wid >> 2) * 64;
    int g  = lane >> 2, tq = lane & 3;

    int bm = blockIdx.x * 128;      // x fastest over M -> B tile shared across wave
    int bn = blockIdx.y * 128;

    const float* Arow = A  + (size_t)bm * H_;
    const float* Brow = Bw + (size_t)bn * H_;

    float c[2][8][4];
#pragma unroll
    for (int mt = 0; mt < 2; mt++)
#pragma unroll
        for (int nt = 0; nt < 8; nt++)
#pragma unroll
            for (int i = 0; i < 4; i++) c[mt][nt][i] = 0.f;

    // loader: 512 A items + 512 B items of 16B each, 4 per thread
    auto load_stage = [&](int st, int koff) {
        float* As = sm + st * (2 * STG_W);
        float* Bs = As + STG_W;
#pragma unroll
        for (int j = 0; j < 4; j++) {
            int item = tid + j * 256;            // 0..1023
            int r = (item & 511) >> 2, q = (item & 3) * 4;
            if (item < 512)
                cpa16(smem_u32(&As[r * TKS + q]), Arow + (size_t)r * H_ + koff + q);
            else
                cpa16(smem_u32(&Bs[r * TKS + q]), Brow + (size_t)r * H_ + koff + q);
        }
        asm volatile("cp.async.commit_group;" ::: "memory");
    };

    load_stage(0, 0);
    load_stage(1, 16);

    for (int cc = 0; cc < 64; cc++) {
        asm volatile("cp.async.wait_group 1;" ::: "memory");
        __syncthreads();

        if (cc + 2 < 64) load_stage((cc + 2) % NST, (cc + 2) * 16);

        const float* As = sm + (cc % NST) * (2 * STG_W);
        const float* Bs = As + STG_W;

#pragma unroll
        for (int ks = 0; ks < 2; ks++) {
            int kb = ks * 8;
            uint32_t a[2][4];
#pragma unroll
            for (int mt = 0; mt < 2; mt++) {
                int m = wm + mt * 16 + g;
                a[mt][0] = __float_as_uint(As[m * TKS + kb + tq]);
                a[mt][1] = __float_as_uint(As[(m + 8) * TKS + kb + tq]);
                a[mt][2] = __float_as_uint(As[m * TKS + kb + tq + 4]);
                a[mt][3] = __float_as_uint(As[(m + 8) * TKS + kb + tq + 4]);
            }
            uint32_t b[8][2];
#pragma unroll
            for (int nt = 0; nt < 8; nt++) {
                int n = wn + nt * 8 + g;
                b[nt][0] = __float_as_uint(Bs[n * TKS + kb + tq]);
                b[nt][1] = __float_as_uint(Bs[n * TKS + kb + tq + 4]);
            }
#pragma unroll
            for (int mt = 0; mt < 2; mt++)
#pragma unroll
                for (int nt = 0; nt < 8; nt++) {
                    asm volatile(
                        "mma.sync.aligned.m16n8k8.row.col.f32.tf32.tf32.f32 "
                        "{%0,%1,%2,%3}, {%4,%5,%6,%7}, {%8,%9}, {%0,%1,%2,%3};\n"
                        : "+f"(c[mt][nt][0]), "+f"(c[mt][nt][1]),
                          "+f"(c[mt][nt][2]), "+f"(c[mt][nt][3])
                        : "r"(a[mt][0]), "r"(a[mt][1]), "r"(a[mt][2]), "r"(a[mt][3]),
                          "r"(b[nt][0]), "r"(b[nt][1]));
                }
        }
        __syncthreads();
    }

    // epilogue: bias + scatter
#pragma unroll
    for (int nt = 0; nt < 8; nt++) {
        int col = bn + wn + nt * 8 + tq * 2;
        float bv0 = bias[col], bv1 = bias[col + 1];
#pragma unroll
        for (int mt = 0; mt < 2; mt++) {
            int m0 = bm + wm + mt * 16 + g;
            {
                int bb = m0 & 3, tt = m0 >> 2;
                float2 o = make_float2(c[mt][nt][0] + bv0, c[mt][nt][1] + bv1);
                *(float2*)(Cout + ((size_t)bb * S_ + tt) * (size_t)V_ + col) = o;
            }
            {
                int m1 = m0 + 8;
                int bb = m1 & 3, tt = m1 >> 2;
                float2 o = make_float2(c[mt][nt][2] + bv0, c[mt][nt][3] + bv1);
                *(float2*)(Cout + ((size_t)bb * S_ + tt) * (size_t)V_ + col) = o;
            }
        }
    }
}

// ---------------- launch ----------------
extern "C" void kernel_launch(void* const* d_in, const int* in_sizes, int n_in,
                              void* d_out, int out_size)
{
    const int*   ids  = (const int*)  d_in[0];
    const float* tok  = (const float*)d_in[1];
    const float* pos  = (const float*)d_in[2];
    const float* W0   = (const float*)d_in[3];
    const float* b0   = (const float*)d_in[4];
    const float* W1   = (const float*)d_in[5];
    const float* b1   = (const float*)d_in[6];
    const float* Wout = (const float*)d_in[7];
    const float* bout = (const float*)d_in[8];
    const float* Wc   = (const float*)d_in[9];
    const float* bc   = (const float*)d_in[10];

    float* out  = (float*)d_out;                         // logits [B,S,V]
    float* traj = out + (size_t)B_ * S_ * V_;            // traj   [B,S,C]

    float *pX, *pZ, *pPS, *pHr, *pWr;
    cudaGetSymbolAddress((void**)&pX,  g_X);
    cudaGetSymbolAddress((void**)&pZ,  g_Z);
    cudaGetSymbolAddress((void**)&pPS, g_PS);
    cudaGetSymbolAddress((void**)&pHr, g_Hr);
    cudaGetSymbolAddress((void**)&pWr, g_Wr);

    const int recur_smem = 40 * 1024 * 4;                 // 160 KB
    const int mma_smem   = NST * 2 * STG_W * 4;           // 3*2*2560*4 = 61440 B
    cudaFuncSetAttribute(recur2,     cudaFuncAttributeMaxDynamicSharedMemorySize, recur_smem);
    cudaFuncSetAttribute(mma_logits, cudaFuncAttributeMaxDynamicSharedMemorySize, mma_smem);

    reset_kernel<<<16, 256>>>();
    embed_kernel<<<S_ * B_, 128>>>(ids, tok, pos);
    // Z = X @ W0x^T + b0   (M=4096, N=1024, K=512)
    sgemm_tn<<<dim3(H_ / BN, (S_ * B_) / BM), 256>>>(pX, E_, W0, E_ + C_, b0, pZ, E_, H_, 0);
    // precompute M = W0c@Wc, v = W0c@bc, round Wout to tf32
    mcomp_kernel<<<dim3(4, 1024), 256>>>(W0, Wc);
    vcomp_kernel<<<4, 256>>>(W0, bc);
    roundw_kernel<<<2048, 256>>>(Wout, V_ * H_ / 4);
    // sequential recurrence (u-space) -> g_H1 (exact), g_Hr (tf32)
    recur2<<<GR, 512, recur_smem>>>(W1, b1);
    // traj = Wc @ prefix(h1) + t*bc
    ps_kernel<<<16, 256>>>();
    sgemm_tn<<<dim3(C_ / BN, (S_ * B_) / BM), 256>>>(pPS, H_, Wc, H_, bc, traj, H_, C_, 2);
    // logits = Hr @ Wr^T + bout  (tf32 mma.sync), scatter to [B,S,V]
    mma_logits<<<dim3((S_ * B_) / 128, V_ / 128), 256, mma_smem>>>(pHr, pWr, bout, out);
}

// round 11
// speedup vs baseline: 1.7940x; 1.1992x over previous
#include <cuda_runtime.h>
#include <cstdint>

#define B_ 4
#define S_ 1024
#define E_ 512
#define C_ 256
#define H_ 1024
#define V_ 32000
#define GR 128    // CTAs in persistent recurrence (co-resident, 1/SM)

// ---------------- scratch device globals ----------------
__device__ float g_X [S_ * B_ * E_];    // embeddings [r=t*4+b][E]
__device__ float g_Z [S_ * B_ * H_];    // X@W0x^T + b0
__device__ float g_H1[S_ * B_ * H_];    // exact h1 [r][H]   (traj prefix)
__device__ float g_Hr[S_ * B_ * H_];    // tf32-rounded h1   (GEMM A operand)
__device__ float g_PS[S_ * B_ * H_];    // exclusive prefix sums of h1
__device__ float g_Wr[(size_t)V_ * H_]; // tf32-rounded Wout
__device__ float g_M [H_ * H_];         // W0c @ Wc
__device__ float g_v [H_];              // W0c @ bc
__device__ float g_u  [H_ * B_];        // u state [k][b]
__device__ float g_h1s[H_ * B_];        // current h1 [k][b]
__device__ unsigned g_ctr;

__device__ __forceinline__ uint32_t f2tf(float f)
{
    uint32_t r;
    asm("cvt.rna.tf32.f32 %0, %1;" : "=r"(r) : "f"(f));
    return r;
}

__global__ void reset_kernel()
{
    int i = blockIdx.x * blockDim.x + threadIdx.x;
    if (i < H_ * B_) g_u[i] = 0.f;
    if (i == 0) g_ctr = 0u;
}

// ---------------- embedding ----------------
__global__ void embed_kernel(const int* __restrict__ ids,
                             const float* __restrict__ tok,
                             const float* __restrict__ pos)
{
    int r = blockIdx.x;            // r = t*4 + b
    int t = r >> 2, b = r & 3;
    int id = ids[b * S_ + t];
    const float4* tp = (const float4*)(tok + (size_t)id * E_);
    const float4* pp = (const float4*)(pos + (size_t)t * E_);
    float4* xp = (float4*)(g_X + (size_t)r * E_);
    int e = threadIdx.x;
    float4 a = tp[e], p = pp[e];
    xp[e] = make_float4(a.x + p.x, a.y + p.y, a.z + p.z, a.w + p.w);
}

// ---------------- M = W0c @ Wc  and  v = W0c @ bc ----------------
__global__ void mcomp_kernel(const float* __restrict__ W0,
                             const float* __restrict__ Wc)
{
    int j = blockIdx.x * 256 + threadIdx.x;   // 0..1023
    int i = blockIdx.y;                       // 0..1023
    const float* w0r = W0 + (size_t)i * (E_ + C_) + E_;
    float acc = 0.f;
#pragma unroll 4
    for (int c = 0; c < C_; c++)
        acc += w0r[c] * Wc[(size_t)c * H_ + j];
    g_M[(size_t)i * H_ + j] = acc;
}

__global__ void vcomp_kernel(const float* __restrict__ W0,
                             const float* __restrict__ bc)
{
    int i = blockIdx.x * 256 + threadIdx.x;
    if (i >= H_) return;
    const float* w0r = W0 + (size_t)i * (E_ + C_) + E_;
    float acc = 0.f;
#pragma unroll 4
    for (int c = 0; c < C_; c++) acc += w0r[c] * bc[c];
    g_v[i] = acc;
}

// ---------------- round Wout to tf32 (rna) ----------------
__global__ void roundw_kernel(const float* __restrict__ src, int n4)
{
    int i = blockIdx.x * blockDim.x + threadIdx.x;
    int stride = gridDim.x * blockDim.x;
    for (; i < n4; i += stride) {
        float4 vv = ((const float4*)src)[i];
        uint4 o = make_uint4(f2tf(vv.x), f2tf(vv.y), f2tf(vv.z), f2tf(vv.w));
        ((uint4*)g_Wr)[i] = o;
    }
}

// ---------------- fp32 SGEMM: C = A[M,K] @ Bw[N,K]^T + bias ----------------
// mode 0: plain row-major out.  mode 2: traj scatter (b=m&3,t=m>>2), bias*t.
#define BM 128
#define BN 128
#define BK 16
#define PADW 132

__global__ __launch_bounds__(256, 2) void sgemm_tn(
    const float* __restrict__ A, int lda,
    const float* __restrict__ Bw, int ldb,
    const float* __restrict__ bias,
    float* __restrict__ Cout,
    int K, int Nout, int mode)
{
    __shared__ float As[BK][PADW];
    __shared__ float Bs[BK][PADW];

    int tid = threadIdx.x;
    int tx = tid & 15, ty = tid >> 4;
    int bm = blockIdx.y * BM, bn = blockIdx.x * BN;

    float acc[8][8];
#pragma unroll
    for (int i = 0; i < 8; i++)
#pragma unroll
        for (int j = 0; j < 8; j++) acc[i][j] = 0.f;

    int lrow = tid >> 2;
    int lkq  = (tid & 3) * 4;

    for (int kt = 0; kt < K; kt += BK) {
#pragma unroll
        for (int h = 0; h < 2; h++) {
            int row = lrow + h * 64;
            float4 va = *(const float4*)(A  + (size_t)(bm + row) * lda + kt + lkq);
            As[lkq + 0][row] = va.x; As[lkq + 1][row] = va.y;
            As[lkq + 2][row] = va.z; As[lkq + 3][row] = va.w;
            float4 vb = *(const float4*)(Bw + (size_t)(bn + row) * ldb + kt + lkq);
            Bs[lkq + 0][row] = vb.x; Bs[lkq + 1][row] = vb.y;
            Bs[lkq + 2][row] = vb.z; Bs[lkq + 3][row] = vb.w;
        }
        __syncthreads();
#pragma unroll
        for (int kk = 0; kk < BK; kk++) {
            float a[8], b[8];
            *(float4*)(a)     = *(const float4*)&As[kk][ty * 8];
            *(float4*)(a + 4) = *(const float4*)&As[kk][ty * 8 + 4];
            *(float4*)(b)     = *(const float4*)&Bs[kk][tx * 8];
            *(float4*)(b + 4) = *(const float4*)&Bs[kk][tx * 8 + 4];
#pragma unroll
            for (int i = 0; i < 8; i++)
#pragma unroll
                for (int j = 0; j < 8; j++)
                    acc[i][j] += a[i] * b[j];
        }
        __syncthreads();
    }

    float bv[8];
#pragma unroll
    for (int j = 0; j < 8; j++) bv[j] = bias[bn + tx * 8 + j];

#pragma unroll
    for (int i = 0; i < 8; i++) {
        int m = bm + ty * 8 + i;
        size_t base;
        float bsc = 1.f;
        if (mode == 2) {
            int bb = m & 3, tt = m >> 2;
            base = ((size_t)bb * S_ + tt) * (size_t)Nout;
            bsc = (float)tt;
        } else {
            base = (size_t)m * (size_t)Nout;
        }
        float4 o0, o1;
        o0.x = acc[i][0] + bv[0] * bsc; o0.y = acc[i][1] + bv[1] * bsc;
        o0.z = acc[i][2] + bv[2] * bsc; o0.w = acc[i][3] + bv[3] * bsc;
        o1.x = acc[i][4] + bv[4] * bsc; o1.y = acc[i][5] + bv[5] * bsc;
        o1.z = acc[i][6] + bv[6] * bsc; o1.w = acc[i][7] + bv[7] * bsc;
        *(float4*)(Cout + base + bn + tx * 8)     = o0;
        *(float4*)(Cout + base + bn + tx * 8 + 4) = o1;
    }
}

// ---------------- global barrier ----------------
__device__ __forceinline__ void gbar(unsigned target)
{
    __syncthreads();
    if (threadIdx.x == 0) {
        __threadfence();
        asm volatile("red.release.gpu.add.u32 [%0], %1;" :: "l"(&g_ctr), "r"(1u) : "memory");
        unsigned v;
        do {
            asm volatile("ld.acquire.gpu.u32 %0, [%1];" : "=r"(v) : "l"(&g_ctr) : "memory");
        } while (v < target);
    }
    __syncthreads();
}

__device__ __forceinline__ float wsum(float v)
{
    v += __shfl_down_sync(0xffffffffu, v, 16);
    v += __shfl_down_sync(0xffffffffu, v, 8);
    v += __shfl_down_sync(0xffffffffu, v, 4);
    v += __shfl_down_sync(0xffffffffu, v, 2);
    v += __shfl_down_sync(0xffffffffu, v, 1);
    return v;
}

// ---------------- persistent u-space recurrence ----------------
// 128 CTAs x 256 threads.  CTA c owns h-rows [8c, 8c+8).
// Per step: recompute full h0 = relu(Z_t + u) locally (no barrier),
//   phase A: h1[r] = relu(W1[r]·h0 + b1)          | gbar
//   phase B: u[r] += M[r]·h1 + v[r]               | gbar
// dyn smem: sW1[8][1024] | sM[8][1024] | sh0[1024*4] | sh1[1024*4]  = 96 KB
__global__ __launch_bounds__(256, 1) void recur2(
    const float* __restrict__ W1, const float* __restrict__ b1)
{
    extern __shared__ float smf[];
    float* sW1 = smf;                  // 8*1024
    float* sM  = smf + 8 * 1024;       // 8*1024
    float* sh0 = smf + 16 * 1024;      // 1024*4
    float* sh1 = smf + 20 * 1024;      // 1024*4

    int c = blockIdx.x, tid = threadIdx.x;
    int w = tid >> 5, lane = tid & 31;
    int rowbase = c * 8;
    int r = rowbase + w;               // this warp's global h-row

    for (int i = tid; i < 8 * 256; i += 256) {       // 8 rows x 256 float4
        int j = i >> 8, kq = (i & 255) * 4;
        *(float4*)&sW1[j * 1024 + kq] = *(const float4*)(W1 + (size_t)(rowbase + j) * H_ + kq);
        *(float4*)&sM [j * 1024 + kq] = *(const float4*)(g_M + (size_t)(rowbase + j) * H_ + kq);
    }
    float rb1 = b1[r];
    float rv  = g_v[r];
    __syncthreads();

    unsigned bar = 0;
    for (int t = 0; t < S_; t++) {
        int t4 = t * 4;
        // ---- stage full h0 = relu(Z_t + u) into smem ----
#pragma unroll
        for (int h = 0; h < 4; h++) {
            int k = tid + h * 256;
            float4 uv = *(const float4*)(g_u + k * 4);
            float z0 = g_Z[(size_t)(t4 + 0) * H_ + k];
            float z1 = g_Z[(size_t)(t4 + 1) * H_ + k];
            float z2 = g_Z[(size_t)(t4 + 2) * H_ + k];
            float z3 = g_Z[(size_t)(t4 + 3) * H_ + k];
            float4 h0;
            h0.x = fmaxf(z0 + uv.x, 0.f); h0.y = fmaxf(z1 + uv.y, 0.f);
            h0.z = fmaxf(z2 + uv.z, 0.f); h0.w = fmaxf(z3 + uv.w, 0.f);
            *(float4*)&sh0[k * 4] = h0;
        }
        __syncthreads();

        // ---- phase A: h1[r] = relu(W1[r]·h0 + b1) ----
        {
            float a0 = 0.f, a1 = 0.f, a2 = 0.f, a3 = 0.f;
            const float* wr = sW1 + w * 1024;
#pragma unroll 8
            for (int i = 0; i < 32; i++) {
                int k = lane + i * 32;
                float wv = wr[k];
                float4 hv = *(const float4*)&sh0[k * 4];
                a0 += wv * hv.x; a1 += wv * hv.y; a2 += wv * hv.z; a3 += wv * hv.w;
            }
            a0 = wsum(a0); a1 = wsum(a1); a2 = wsum(a2); a3 = wsum(a3);
            if (lane == 0) {
                float4 h;
                h.x = fmaxf(a0 + rb1, 0.f); h.y = fmaxf(a1 + rb1, 0.f);
                h.z = fmaxf(a2 + rb1, 0.f); h.w = fmaxf(a3 + rb1, 0.f);
                *(float4*)(g_h1s + r * 4) = h;
                g_H1[(size_t)(t4 + 0) * H_ + r] = h.x;
                g_H1[(size_t)(t4 + 1) * H_ + r] = h.y;
                g_H1[(size_t)(t4 + 2) * H_ + r] = h.z;
                g_H1[(size_t)(t4 + 3) * H_ + r] = h.w;
                g_Hr[(size_t)(t4 + 0) * H_ + r] = __uint_as_float(f2tf(h.x));
                g_Hr[(size_t)(t4 + 1) * H_ + r] = __uint_as_float(f2tf(h.y));
                g_Hr[(size_t)(t4 + 2) * H_ + r] = __uint_as_float(f2tf(h.z));
                g_Hr[(size_t)(t4 + 3) * H_ + r] = __uint_as_float(f2tf(h.w));
            }
        }
        gbar(++bar * GR);

        // ---- stage full h1 into smem ----
#pragma unroll
        for (int h = 0; h < 4; h++) {
            int k = tid + h * 256;
            *(float4*)&sh1[k * 4] = *(const float4*)(g_h1s + k * 4);
        }
        __syncthreads();

        // ---- phase B: u[r] += M[r]·h1 + v[r] ----
        {
            float a0 = 0.f, a1 = 0.f, a2 = 0.f, a3 = 0.f;
            const float* mr = sM + w * 1024;
#pragma unroll 8
            for (int i = 0; i < 32; i++) {
                int k = lane + i * 32;
                float wv = mr[k];
                float4 hv = *(const float4*)&sh1[k * 4];
                a0 += wv * hv.x; a1 += wv * hv.y; a2 += wv * hv.z; a3 += wv * hv.w;
            }
            a0 = wsum(a0); a1 = wsum(a1); a2 = wsum(a2); a3 = wsum(a3);
            if (lane == 0) {
                float4 u = *(const float4*)(g_u + r * 4);
                u.x += a0 + rv; u.y += a1 + rv; u.z += a2 + rv; u.w += a3 + rv;
                *(float4*)(g_u + r * 4) = u;
            }
        }
        gbar(++bar * GR);
    }
}

// ---------------- exclusive prefix sums of h1 over t ----------------
__global__ void ps_kernel()
{
    int idx = blockIdx.x * 256 + threadIdx.x;  // 0..4095
    int k = idx & 1023, b = idx >> 10;
    float acc = 0.f;
    for (int t = 0; t < S_; t += 4) {
        float x0 = g_H1[(size_t)((t + 0) * 4 + b) * H_ + k];
        float x1 = g_H1[(size_t)((t + 1) * 4 + b) * H_ + k];
        float x2 = g_H1[(size_t)((t + 2) * 4 + b) * H_ + k];
        float x3 = g_H1[(size_t)((t + 3) * 4 + b) * H_ + k];
        g_PS[(size_t)((t + 0) * 4 + b) * H_ + k] = acc; acc += x0;
        g_PS[(size_t)((t + 1) * 4 + b) * H_ + k] = acc; acc += x1;
        g_PS[(size_t)((t + 2) * 4 + b) * H_ + k] = acc; acc += x2;
        g_PS[(size_t)((t + 3) * 4 + b) * H_ + k] = acc; acc += x3;
    }
}

// ============ tf32 mma.sync logits GEMM: 128x256 tile, 8 warps of 64x64 ============
// C[m][n] = sum_k Hr[m][k]*Wr[n][k] + bout[n], scatter row m -> [b=m&3][t=m>>2].
// 3-stage cp.async, BK=16, 1 CTA/SM.
#define TKS 20                         // smem row stride words (conflict-free frags)
#define A_W (128 * TKS)
#define B_W (256 * TKS)
#define STW (A_W + B_W)                // stage words = 7680 (30 KB)
#define NST 3

__device__ __forceinline__ void cpa16(uint32_t dst, const float* src)
{
    asm volatile("cp.async.cg.shared.global [%0], [%1], 16;" :: "r"(dst), "l"(src));
}

static __device__ __forceinline__ uint32_t smem_u32(const void* p)
{
    uint32_t a;
    asm("{ .reg .u64 t; cvta.to.shared.u64 t, %1; cvt.u32.u64 %0, t; }" : "=r"(a) : "l"(p));
    return a;
}

__global__ __launch_bounds__(256, 1) void mma_logits(
    const float* __restrict__ A,    // g_Hr [4096][1024]
    const float* __restrict__ Bw,   // g_Wr [32000][1024]
    const float* __restrict__ bias,
    float* __restrict__ Cout)
{
    extern __shared__ float sm[];
    int tid = threadIdx.x;
    int lane = tid & 31, wid = tid >> 5;
    int wm = (wid & 1) * 64;        // 2 warps along M
    int wn = (wid >> 1) * 64;       // 4 warps along N
    int g  = lane >> 2, tq = lane & 3;

    int bm = blockIdx.x * 128;      // x fastest over M -> A stays L2-resident
    int bn = blockIdx.y * 256;

    const float* Arow = A  + (size_t)bm * H_;
    const float* Brow = Bw + (size_t)bn * H_;

    float c[4][8][4];
#pragma unroll
    for (int mt = 0; mt < 4; mt++)
#pragma unroll
        for (int nt = 0; nt < 8; nt++)
#pragma unroll
            for (int i = 0; i < 4; i++) c[mt][nt][i] = 0.f;

    // loader: A 512 items + B 1024 items of 16B, 6 per thread
    auto load_stage = [&](int st, int koff) {
        float* As = sm + st * STW;
        float* Bs = As + A_W;
#pragma unroll
        for (int j = 0; j < 6; j++) {
            int item = tid + j * 256;            // 0..1535
            if (item < 512) {
                int r = item >> 2, q = (item & 3) * 4;
                cpa16(smem_u32(&As[r * TKS + q]), Arow + (size_t)r * H_ + koff + q);
            } else {
                int it = item - 512;
                int r = it >> 2, q = (it & 3) * 4;
                cpa16(smem_u32(&Bs[r * TKS + q]), Brow + (size_t)r * H_ + koff + q);
            }
        }
        asm volatile("cp.async.commit_group;" ::: "memory");
    };

    load_stage(0, 0);
    load_stage(1, 16);

    for (int cc = 0; cc < 64; cc++) {
        asm volatile("cp.async.wait_group 1;" ::: "memory");
        __syncthreads();

        if (cc + 2 < 64) load_stage((cc + 2) % NST, (cc + 2) * 16);

        const float* As = sm + (cc % NST) * STW;
        const float* Bs = As + A_W;

#pragma unroll
        for (int ks = 0; ks < 2; ks++) {
            int kb = ks * 8;
            uint32_t a[4][4];
#pragma unroll
            for (int mt = 0; mt < 4; mt++) {
                int m = wm + mt * 16 + g;
                a[mt][0] = __float_as_uint(As[m * TKS + kb + tq]);
                a[mt][1] = __float_as_uint(As[(m + 8) * TKS + kb + tq]);
                a[mt][2] = __float_as_uint(As[m * TKS + kb + tq + 4]);
                a[mt][3] = __float_as_uint(As[(m + 8) * TKS + kb + tq + 4]);
            }
            uint32_t b[8][2];
#pragma unroll
            for (int nt = 0; nt < 8; nt++) {
                int n = wn + nt * 8 + g;
                b[nt][0] = __float_as_uint(Bs[n * TKS + kb + tq]);
                b[nt][1] = __float_as_uint(Bs[n * TKS + kb + tq + 4]);
            }
#pragma unroll
            for (int mt = 0; mt < 4; mt++)
#pragma unroll
                for (int nt = 0; nt < 8; nt++) {
                    asm volatile(
                        "mma.sync.aligned.m16n8k8.row.col.f32.tf32.tf32.f32 "
                        "{%0,%1,%2,%3}, {%4,%5,%6,%7}, {%8,%9}, {%0,%1,%2,%3};\n"
                        : "+f"(c[mt][nt][0]), "+f"(c[mt][nt][1]),
                          "+f"(c[mt][nt][2]), "+f"(c[mt][nt][3])
                        : "r"(a[mt][0]), "r"(a[mt][1]), "r"(a[mt][2]), "r"(a[mt][3]),
                          "r"(b[nt][0]), "r"(b[nt][1]));
                }
        }
        __syncthreads();
    }

    // epilogue: bias + scatter
#pragma unroll
    for (int nt = 0; nt < 8; nt++) {
        int col = bn + wn + nt * 8 + tq * 2;
        float bv0 = bias[col], bv1 = bias[col + 1];
#pragma unroll
        for (int mt = 0; mt < 4; mt++) {
            int m0 = bm + wm + mt * 16 + g;
            {
                int bb = m0 & 3, tt = m0 >> 2;
                float2 o = make_float2(c[mt][nt][0] + bv0, c[mt][nt][1] + bv1);
                *(float2*)(Cout + ((size_t)bb * S_ + tt) * (size_t)V_ + col) = o;
            }
            {
                int m1 = m0 + 8;
                int bb = m1 & 3, tt = m1 >> 2;
                float2 o = make_float2(c[mt][nt][2] + bv0, c[mt][nt][3] + bv1);
                *(float2*)(Cout + ((size_t)bb * S_ + tt) * (size_t)V_ + col) = o;
            }
        }
    }
}

// ---------------- launch ----------------
extern "C" void kernel_launch(void* const* d_in, const int* in_sizes, int n_in,
                              void* d_out, int out_size)
{
    const int*   ids  = (const int*)  d_in[0];
    const float* tok  = (const float*)d_in[1];
    const float* pos  = (const float*)d_in[2];
    const float* W0   = (const float*)d_in[3];
    const float* b0   = (const float*)d_in[4];
    const float* W1   = (const float*)d_in[5];
    const float* b1   = (const float*)d_in[6];
    const float* Wout = (const float*)d_in[7];
    const float* bout = (const float*)d_in[8];
    const float* Wc   = (const float*)d_in[9];
    const float* bc   = (const float*)d_in[10];

    float* out  = (float*)d_out;                         // logits [B,S,V]
    float* traj = out + (size_t)B_ * S_ * V_;            // traj   [B,S,C]

    float *pX, *pZ, *pPS, *pHr, *pWr;
    cudaGetSymbolAddress((void**)&pX,  g_X);
    cudaGetSymbolAddress((void**)&pZ,  g_Z);
    cudaGetSymbolAddress((void**)&pPS, g_PS);
    cudaGetSymbolAddress((void**)&pHr, g_Hr);
    cudaGetSymbolAddress((void**)&pWr, g_Wr);

    const int recur_smem = 24 * 1024 * 4;                 // 96 KB
    const int mma_smem   = NST * STW * 4;                 // 3*7680*4 = 92160 B
    cudaFuncSetAttribute(recur2,     cudaFuncAttributeMaxDynamicSharedMemorySize, recur_smem);
    cudaFuncSetAttribute(mma_logits, cudaFuncAttributeMaxDynamicSharedMemorySize, mma_smem);

    reset_kernel<<<16, 256>>>();
    embed_kernel<<<S_ * B_, 128>>>(ids, tok, pos);
    // Z = X @ W0x^T + b0   (M=4096, N=1024, K=512)
    sgemm_tn<<<dim3(H_ / BN, (S_ * B_) / BM), 256>>>(pX, E_, W0, E_ + C_, b0, pZ, E_, H_, 0);
    // precompute M = W0c@Wc, v = W0c@bc, round Wout to tf32
    mcomp_kernel<<<dim3(4, 1024), 256>>>(W0, Wc);
    vcomp_kernel<<<4, 256>>>(W0, bc);
    roundw_kernel<<<2048, 256>>>(Wout, V_ * H_ / 4);
    // sequential recurrence (u-space) -> g_H1 (exact), g_Hr (tf32)
    recur2<<<GR, 256, recur_smem>>>(W1, b1);
    // traj = Wc @ prefix(h1) + t*bc
    ps_kernel<<<16, 256>>>();
    sgemm_tn<<<dim3(C_ / BN, (S_ * B_) / BM), 256>>>(pPS, H_, Wc, H_, bc, traj, H_, C_, 2);
    // logits = Hr @ Wr^T + bout  (tf32 mma.sync 128x256), scatter to [B,S,V]
    mma_logits<<<dim3((S_ * B_) / 128, V_ / 256), 256, mma_smem>>>(pHr, pWr, bout, out);
}

// round 15
// speedup vs baseline: 2.0956x; 1.1681x over previous
#include <cuda_runtime.h>
#include <cstdint>

#define B_ 4
#define S_ 1024
#define E_ 512
#define C_ 256
#define H_ 1024
#define V_ 32000
#define GR 128    // CTAs in persistent recurrence (co-resident, 1/SM)

// ---------------- scratch device globals ----------------
__device__ float g_X [S_ * B_ * E_];    // embeddings [r=t*4+b][E]
__device__ float g_Z [S_ * B_ * H_];    // X@W0x^T + b0
__device__ float g_H1[S_ * B_ * H_];    // exact h1 [r][H]   (traj prefix)
__device__ float g_Hr[S_ * B_ * H_];    // tf32-rounded h1   (GEMM A operand)
__device__ float g_PS[S_ * B_ * H_];    // exclusive prefix sums of h1
__device__ float g_Wr[(size_t)V_ * H_]; // tf32-rounded Wout
__device__ float g_M [H_ * H_];         // W0c @ Wc
__device__ float g_v [H_];              // W0c @ bc
__device__ float g_u  [H_ * B_];        // u state [k][b]
__device__ float g_h1s[H_ * B_];        // current h1 [k][b]
__device__ unsigned g_ctr;

__device__ __forceinline__ uint32_t f2tf(float f)
{
    uint32_t r;
    asm("cvt.rna.tf32.f32 %0, %1;" : "=r"(r) : "f"(f));
    return r;
}

__global__ void reset_kernel()
{
    int i = blockIdx.x * blockDim.x + threadIdx.x;
    if (i < H_ * B_) g_u[i] = 0.f;
    if (i == 0) g_ctr = 0u;
}

// ---------------- embedding ----------------
__global__ void embed_kernel(const int* __restrict__ ids,
                             const float* __restrict__ tok,
                             const float* __restrict__ pos)
{
    int r = blockIdx.x;            // r = t*4 + b
    int t = r >> 2, b = r & 3;
    int id = ids[b * S_ + t];
    const float4* tp = (const float4*)(tok + (size_t)id * E_);
    const float4* pp = (const float4*)(pos + (size_t)t * E_);
    float4* xp = (float4*)(g_X + (size_t)r * E_);
    int e = threadIdx.x;
    float4 a = tp[e], p = pp[e];
    xp[e] = make_float4(a.x + p.x, a.y + p.y, a.z + p.z, a.w + p.w);
}

// ---------------- M = W0c @ Wc  and  v = W0c @ bc ----------------
__global__ void mcomp_kernel(const float* __restrict__ W0,
                             const float* __restrict__ Wc)
{
    int j = blockIdx.x * 256 + threadIdx.x;   // 0..1023
    int i = blockIdx.y;                       // 0..1023
    const float* w0r = W0 + (size_t)i * (E_ + C_) + E_;
    float acc = 0.f;
#pragma unroll 4
    for (int c = 0; c < C_; c++)
        acc += w0r[c] * Wc[(size_t)c * H_ + j];
    g_M[(size_t)i * H_ + j] = acc;
}

__global__ void vcomp_kernel(const float* __restrict__ W0,
                             const float* __restrict__ bc)
{
    int i = blockIdx.x * 256 + threadIdx.x;
    if (i >= H_) return;
    const float* w0r = W0 + (size_t)i * (E_ + C_) + E_;
    float acc = 0.f;
#pragma unroll 4
    for (int c = 0; c < C_; c++) acc += w0r[c] * bc[c];
    g_v[i] = acc;
}

// ---------------- round Wout to tf32 (rna) ----------------
__global__ void roundw_kernel(const float* __restrict__ src, int n4)
{
    int i = blockIdx.x * blockDim.x + threadIdx.x;
    int stride = gridDim.x * blockDim.x;
    for (; i < n4; i += stride) {
        float4 vv = ((const float4*)src)[i];
        uint4 o = make_uint4(f2tf(vv.x), f2tf(vv.y), f2tf(vv.z), f2tf(vv.w));
        ((uint4*)g_Wr)[i] = o;
    }
}

// ---------------- fp32 SGEMM: C = A[M,K] @ Bw[N,K]^T + bias ----------------
#define BM 128
#define BN 128
#define BK 16
#define PADW 132

__global__ __launch_bounds__(256, 2) void sgemm_tn(
    const float* __restrict__ A, int lda,
    const float* __restrict__ Bw, int ldb,
    const float* __restrict__ bias,
    float* __restrict__ Cout,
    int K, int Nout, int mode)
{
    __shared__ float As[BK][PADW];
    __shared__ float Bs[BK][PADW];

    int tid = threadIdx.x;
    int tx = tid & 15, ty = tid >> 4;
    int bm = blockIdx.y * BM, bn = blockIdx.x * BN;

    float acc[8][8];
#pragma unroll
    for (int i = 0; i < 8; i++)
#pragma unroll
        for (int j = 0; j < 8; j++) acc[i][j] = 0.f;

    int lrow = tid >> 2;
    int lkq  = (tid & 3) * 4;

    for (int kt = 0; kt < K; kt += BK) {
#pragma unroll
        for (int h = 0; h < 2; h++) {
            int row = lrow + h * 64;
            float4 va = *(const float4*)(A  + (size_t)(bm + row) * lda + kt + lkq);
            As[lkq + 0][row] = va.x; As[lkq + 1][row] = va.y;
            As[lkq + 2][row] = va.z; As[lkq + 3][row] = va.w;
            float4 vb = *(const float4*)(Bw + (size_t)(bn + row) * ldb + kt + lkq);
            Bs[lkq + 0][row] = vb.x; Bs[lkq + 1][row] = vb.y;
            Bs[lkq + 2][row] = vb.z; Bs[lkq + 3][row] = vb.w;
        }
        __syncthreads();
#pragma unroll
        for (int kk = 0; kk < BK; kk++) {
            float a[8], b[8];
            *(float4*)(a)     = *(const float4*)&As[kk][ty * 8];
            *(float4*)(a + 4) = *(const float4*)&As[kk][ty * 8 + 4];
            *(float4*)(b)     = *(const float4*)&Bs[kk][tx * 8];
            *(float4*)(b + 4) = *(const float4*)&Bs[kk][tx * 8 + 4];
#pragma unroll
            for (int i = 0; i < 8; i++)
#pragma unroll
                for (int j = 0; j < 8; j++)
                    acc[i][j] += a[i] * b[j];
        }
        __syncthreads();
    }

    float bv[8];
#pragma unroll
    for (int j = 0; j < 8; j++) bv[j] = bias[bn + tx * 8 + j];

#pragma unroll
    for (int i = 0; i < 8; i++) {
        int m = bm + ty * 8 + i;
        size_t base;
        float bsc = 1.f;
        if (mode == 2) {
            int bb = m & 3, tt = m >> 2;
            base = ((size_t)bb * S_ + tt) * (size_t)Nout;
            bsc = (float)tt;
        } else {
            base = (size_t)m * (size_t)Nout;
        }
        float4 o0, o1;
        o0.x = acc[i][0] + bv[0] * bsc; o0.y = acc[i][1] + bv[1] * bsc;
        o0.z = acc[i][2] + bv[2] * bsc; o0.w = acc[i][3] + bv[3] * bsc;
        o1.x = acc[i][4] + bv[4] * bsc; o1.y = acc[i][5] + bv[5] * bsc;
        o1.z = acc[i][6] + bv[6] * bsc; o1.w = acc[i][7] + bv[7] * bsc;
        *(float4*)(Cout + base + bn + tx * 8)     = o0;
        *(float4*)(Cout + base + bn + tx * 8 + 4) = o1;
    }
}

// ---------------- global barrier ----------------
// tid0's __threadfence() (fence.gpu) emits CCTL.IVALL -> whole-SM L1D invalidate,
// so post-poll global reads observe remote CTAs' writes. Do not remove it.
__device__ __forceinline__ void gbar(unsigned target)
{
    __syncthreads();
    if (threadIdx.x == 0) {
        __threadfence();
        asm volatile("red.release.gpu.add.u32 [%0], %1;" :: "l"(&g_ctr), "r"(1u) : "memory");
        unsigned v;
        do {
            asm volatile("ld.acquire.gpu.u32 %0, [%1];" : "=r"(v) : "l"(&g_ctr) : "memory");
        } while (v < target);
    }
    __syncthreads();
}

// multi-value butterfly: reduce v[0..31] across 32 lanes; lane l returns sum of v[l].
__device__ __forceinline__ float red32(const float* v, int lane)
{
    float a[16];
#pragma unroll
    for (int i = 0; i < 16; i++) {
        float s = (lane & 16) ? v[i] : v[i + 16];
        float r = __shfl_xor_sync(0xffffffffu, s, 16);
        a[i] = ((lane & 16) ? v[i + 16] : v[i]) + r;
    }
    float b[8];
#pragma unroll
    for (int i = 0; i < 8; i++) {
        float s = (lane & 8) ? a[i] : a[i + 8];
        float r = __shfl_xor_sync(0xffffffffu, s, 8);
        b[i] = ((lane & 8) ? a[i + 8] : a[i]) + r;
    }
    float c4[4];
#pragma unroll
    for (int i = 0; i < 4; i++) {
        float s = (lane & 4) ? b[i] : b[i + 4];
        float r = __shfl_xor_sync(0xffffffffu, s, 4);
        c4[i] = ((lane & 4) ? b[i + 4] : b[i]) + r;
    }
    float d2[2];
#pragma unroll
    for (int i = 0; i < 2; i++) {
        float s = (lane & 2) ? c4[i] : c4[i + 2];
        float r = __shfl_xor_sync(0xffffffffu, s, 2);
        d2[i] = ((lane & 2) ? c4[i + 2] : c4[i]) + r;
    }
    float s = (lane & 1) ? d2[0] : d2[1];
    float r = __shfl_xor_sync(0xffffffffu, s, 1);
    return ((lane & 1) ? d2[1] : d2[0]) + r;
}

// ---------------- persistent u-space recurrence, K-split ----------------
// 128 CTAs x 256 threads. CTA c owns h-rows [8c, 8c+8).
// Warp w owns k-slice [128w,128w+128); lane l owns k-quad kq = 128w + 4l.
// Weights (W1, M row-slices over own k-quad) live in registers.
// Phase A: h1 = relu(W1·h0 + b1), h0 = relu(Z_t + u) computed per-lane | gbar
// Phase B: u += M·h1 + v                                              | gbar
__global__ __launch_bounds__(256, 1) void recur3(
    const float* __restrict__ W1, const float* __restrict__ b1)
{
    __shared__ float sred[256];        // 8 warps x 32 partials

    int c = blockIdx.x, tid = threadIdx.x;
    int w = tid >> 5, lane = tid & 31;
    int rowbase = c * 8;
    int kq = w * 128 + lane * 4;

    // weights into registers: [row][i] over own k-quad
    float w1a[8][4], ma[8][4];
#pragma unroll
    for (int row = 0; row < 8; row++) {
        float4 wv = *(const float4*)(W1 + (size_t)(rowbase + row) * H_ + kq);
        w1a[row][0] = wv.x; w1a[row][1] = wv.y; w1a[row][2] = wv.z; w1a[row][3] = wv.w;
        float4 mv = *(const float4*)(g_M + (size_t)(rowbase + row) * H_ + kq);
        ma[row][0] = mv.x; ma[row][1] = mv.y; ma[row][2] = mv.z; ma[row][3] = mv.w;
    }
    // finisher-lane constants (tid<32): pair (row = tid>>2, batch = tid&3)
    int fr = rowbase + ((tid & 31) >> 2);
    float rb1 = b1[fr];
    float rv  = g_v[fr];
    float myu = 0.f;                   // owner-resident u value (tid<32 only)

    // prefetch Z for t=0: zpre[b] = Z[(0*4+b)*H + kq..kq+3]
    float4 zpre[4];
#pragma unroll
    for (int b = 0; b < 4; b++)
        zpre[b] = *(const float4*)(g_Z + (size_t)b * H_ + kq);

    unsigned bar = 0;
    for (int t = 0; t < S_; t++) {
        int t4 = t * 4;

        // ---- h0 for own k-quad: h0v[i][b] = relu(z[b][i] + u[i][b]) ----
        float zf[4][4];                // [b][i]
#pragma unroll
        for (int b = 0; b < 4; b++)
            *(float4*)&zf[b][0] = zpre[b];
        float uf[4][4];                // [i][b]
#pragma unroll
        for (int i = 0; i < 4; i++)
            *(float4*)&uf[i][0] = *(const float4*)(g_u + (kq + i) * 4);
        float h0v[4][4];               // [i][b]
#pragma unroll
        for (int i = 0; i < 4; i++)
#pragma unroll
            for (int b = 0; b < 4; b++)
                h0v[i][b] = fmaxf(zf[b][i] + uf[i][b], 0.f);

        // ---- phase A partials: acc[row*4+b] over own 4 k's ----
        {
            float acc[32];
#pragma unroll
            for (int p = 0; p < 32; p++) acc[p] = 0.f;
#pragma unroll
            for (int row = 0; row < 8; row++)
#pragma unroll
                for (int i = 0; i < 4; i++) {
                    float wv = w1a[row][i];
#pragma unroll
                    for (int b = 0; b < 4; b++)
                        acc[row * 4 + b] += wv * h0v[i][b];
                }
            sred[w * 32 + lane] = red32(acc, lane);
        }
        __syncthreads();
        if (tid < 32) {
            float tot = 0.f;
#pragma unroll
            for (int w2 = 0; w2 < 8; w2++) tot += sred[w2 * 32 + tid];
            float h = fmaxf(tot + rb1, 0.f);
            int b = tid & 3;
            g_h1s[fr * 4 + b] = h;
            g_H1[(size_t)(t4 + b) * H_ + fr] = h;
            g_Hr[(size_t)(t4 + b) * H_ + fr] = __uint_as_float(f2tf(h));
        }
        gbar(++bar * GR);

        // ---- phase B: read h1 slice, partials with M ----
        {
            float hf[4][4];            // [i][b]
#pragma unroll
            for (int i = 0; i < 4; i++)
                *(float4*)&hf[i][0] = *(const float4*)(g_h1s + (kq + i) * 4);
            float acc[32];
#pragma unroll
            for (int p = 0; p < 32; p++) acc[p] = 0.f;
#pragma unroll
            for (int row = 0; row < 8; row++)
#pragma unroll
                for (int i = 0; i < 4; i++) {
                    float wv = ma[row][i];
#pragma unroll
                    for (int b = 0; b < 4; b++)
                        acc[row * 4 + b] += wv * hf[i][b];
                }
            sred[w * 32 + lane] = red32(acc, lane);
        }

        // prefetch next step's Z (hides L2 latency under the coming barrier)
        {
            int tn4 = (t + 1 < S_ ? t + 1 : t) * 4;
#pragma unroll
            for (int b = 0; b < 4; b++)
                zpre[b] = *(const float4*)(g_Z + (size_t)(tn4 + b) * H_ + kq);
        }

        __syncthreads();
        if (tid < 32) {
            float tot = 0.f;
#pragma unroll
            for (int w2 = 0; w2 < 8; w2++) tot += sred[w2 * 32 + tid];
            myu += tot + rv;
            g_u[fr * 4 + (tid & 3)] = myu;
        }
        gbar(++bar * GR);
    }
}

// ---------------- exclusive prefix sums of h1 over t ----------------
__global__ void ps_kernel()
{
    int idx = blockIdx.x * 256 + threadIdx.x;  // 0..4095
    int k = idx & 1023, b = idx >> 10;
    float acc = 0.f;
    for (int t = 0; t < S_; t += 4) {
        float x0 = g_H1[(size_t)((t + 0) * 4 + b) * H_ + k];
        float x1 = g_H1[(size_t)((t + 1) * 4 + b) * H_ + k];
        float x2 = g_H1[(size_t)((t + 2) * 4 + b) * H_ + k];
        float x3 = g_H1[(size_t)((t + 3) * 4 + b) * H_ + k];
        g_PS[(size_t)((t + 0) * 4 + b) * H_ + k] = acc; acc += x0;
        g_PS[(size_t)((t + 1) * 4 + b) * H_ + k] = acc; acc += x1;
        g_PS[(size_t)((t + 2) * 4 + b) * H_ + k] = acc; acc += x2;
        g_PS[(size_t)((t + 3) * 4 + b) * H_ + k] = acc; acc += x3;
    }
}

// ============ tf32 mma.sync logits GEMM: 128x256 tile, 8 warps of 64x64 ============
#define TKS 20
#define A_W (128 * TKS)
#define B_W (256 * TKS)
#define STW (A_W + B_W)
#define NST 3

__device__ __forceinline__ void cpa16(uint32_t dst, const float* src)
{
    asm volatile("cp.async.cg.shared.global [%0], [%1], 16;" :: "r"(dst), "l"(src));
}

static __device__ __forceinline__ uint32_t smem_u32(const void* p)
{
    uint32_t a;
    asm("{ .reg .u64 t; cvta.to.shared.u64 t, %1; cvt.u32.u64 %0, t; }" : "=r"(a) : "l"(p));
    return a;
}

__global__ __launch_bounds__(256, 1) void mma_logits(
    const float* __restrict__ A,    // g_Hr [4096][1024]
    const float* __restrict__ Bw,   // g_Wr [32000][1024]
    const float* __restrict__ bias,
    float* __restrict__ Cout)
{
    extern __shared__ float sm[];
    int tid = threadIdx.x;
    int lane = tid & 31, wid = tid >> 5;
    int wm = (wid & 1) * 64;
    int wn = (wid >> 1) * 64;
    int g  = lane >> 2, tq = lane & 3;

    int bm = blockIdx.x * 128;
    int bn = blockIdx.y * 256;

    const float* Arow = A  + (size_t)bm * H_;
    const float* Brow = Bw + (size_t)bn * H_;

    float c[4][8][4];
#pragma unroll
    for (int mt = 0; mt < 4; mt++)
#pragma unroll
        for (int nt = 0; nt < 8; nt++)
#pragma unroll
            for (int i = 0; i < 4; i++) c[mt][nt][i] = 0.f;

    auto load_stage = [&](int st, int koff) {
        float* As = sm + st * STW;
        float* Bs = As + A_W;
#pragma unroll
        for (int j = 0; j < 6; j++) {
            int item = tid + j * 256;
            if (item < 512) {
                int r = item >> 2, q = (item & 3) * 4;
                cpa16(smem_u32(&As[r * TKS + q]), Arow + (size_t)r * H_ + koff + q);
            } else {
                int it = item - 512;
                int r = it >> 2, q = (it & 3) * 4;
                cpa16(smem_u32(&Bs[r * TKS + q]), Brow + (size_t)r * H_ + koff + q);
            }
        }
        asm volatile("cp.async.commit_group;" ::: "memory");
    };

    load_stage(0, 0);
    load_stage(1, 16);

    for (int cc = 0; cc < 64; cc++) {
        asm volatile("cp.async.wait_group 1;" ::: "memory");
        __syncthreads();

        if (cc + 2 < 64) load_stage((cc + 2) % NST, (cc + 2) * 16);

        const float* As = sm + (cc % NST) * STW;
        const float* Bs = As + A_W;

#pragma unroll
        for (int ks = 0; ks < 2; ks++) {
            int kb = ks * 8;
            uint32_t a[4][4];
#pragma unroll
            for (int mt = 0; mt < 4; mt++) {
                int m = wm + mt * 16 + g;
                a[mt][0] = __float_as_uint(As[m * TKS + kb + tq]);
                a[mt][1] = __float_as_uint(As[(m + 8) * TKS + kb + tq]);
                a[mt][2] = __float_as_uint(As[m * TKS + kb + tq + 4]);
                a[mt][3] = __float_as_uint(As[(m + 8) * TKS + kb + tq + 4]);
            }
            uint32_t b[8][2];
#pragma unroll
            for (int nt = 0; nt < 8; nt++) {
                int n = wn + nt * 8 + g;
                b[nt][0] = __float_as_uint(Bs[n * TKS + kb + tq]);
                b[nt][1] = __float_as_uint(Bs[n * TKS + kb + tq + 4]);
            }
#pragma unroll
            for (int mt = 0; mt < 4; mt++)
#pragma unroll
                for (int nt = 0; nt < 8; nt++) {
                    asm volatile(
                        "mma.sync.aligned.m16n8k8.row.col.f32.tf32.tf32.f32 "
                        "{%0,%1,%2,%3}, {%4,%5,%6,%7}, {%8,%9}, {%0,%1,%2,%3};\n"
                        : "+f"(c[mt][nt][0]), "+f"(c[mt][nt][1]),
                          "+f"(c[mt][nt][2]), "+f"(c[mt][nt][3])
                        : "r"(a[mt][0]), "r"(a[mt][1]), "r"(a[mt][2]), "r"(a[mt][3]),
                          "r"(b[nt][0]), "r"(b[nt][1]));
                }
        }
        __syncthreads();
    }

#pragma unroll
    for (int nt = 0; nt < 8; nt++) {
        int col = bn + wn + nt * 8 + tq * 2;
        float bv0 = bias[col], bv1 = bias[col + 1];
#pragma unroll
        for (int mt = 0; mt < 4; mt++) {
            int m0 = bm + wm + mt * 16 + g;
            {
                int bb = m0 & 3, tt = m0 >> 2;
                float2 o = make_float2(c[mt][nt][0] + bv0, c[mt][nt][1] + bv1);
                *(float2*)(Cout + ((size_t)bb * S_ + tt) * (size_t)V_ + col) = o;
            }
            {
                int m1 = m0 + 8;
                int bb = m1 & 3, tt = m1 >> 2;
                float2 o = make_float2(c[mt][nt][2] + bv0, c[mt][nt][3] + bv1);
                *(float2*)(Cout + ((size_t)bb * S_ + tt) * (size_t)V_ + col) = o;
            }
        }
    }
}

// ---------------- launch ----------------
extern "C" void kernel_launch(void* const* d_in, const int* in_sizes, int n_in,
                              void* d_out, int out_size)
{
    const int*   ids  = (const int*)  d_in[0];
    const float* tok  = (const float*)d_in[1];
    const float* pos  = (const float*)d_in[2];
    const float* W0   = (const float*)d_in[3];
    const float* b0   = (const float*)d_in[4];
    const float* W1   = (const float*)d_in[5];
    const float* b1   = (const float*)d_in[6];
    const float* Wout = (const float*)d_in[7];
    const float* bout = (const float*)d_in[8];
    const float* Wc   = (const float*)d_in[9];
    const float* bc   = (const float*)d_in[10];

    float* out  = (float*)d_out;                         // logits [B,S,V]
    float* traj = out + (size_t)B_ * S_ * V_;            // traj   [B,S,C]

    float *pX, *pZ, *pPS, *pHr, *pWr;
    cudaGetSymbolAddress((void**)&pX,  g_X);
    cudaGetSymbolAddress((void**)&pZ,  g_Z);
    cudaGetSymbolAddress((void**)&pPS, g_PS);
    cudaGetSymbolAddress((void**)&pHr, g_Hr);
    cudaGetSymbolAddress((void**)&pWr, g_Wr);

    const int mma_smem = NST * STW * 4;                   // 92160 B
    cudaFuncSetAttribute(mma_logits, cudaFuncAttributeMaxDynamicSharedMemorySize, mma_smem);

    reset_kernel<<<16, 256>>>();
    embed_kernel<<<S_ * B_, 128>>>(ids, tok, pos);
    // Z = X @ W0x^T + b0   (M=4096, N=1024, K=512)
    sgemm_tn<<<dim3(H_ / BN, (S_ * B_) / BM), 256>>>(pX, E_, W0, E_ + C_, b0, pZ, E_, H_, 0);
    // precompute M = W0c@Wc, v = W0c@bc, round Wout to tf32
    mcomp_kernel<<<dim3(4, 1024), 256>>>(W0, Wc);
    vcomp_kernel<<<4, 256>>>(W0, bc);
    roundw_kernel<<<2048, 256>>>(Wout, V_ * H_ / 4);
    // sequential recurrence (u-space, K-split, register weights)
    recur3<<<GR, 256>>>(W1, b1);
    // traj = Wc @ prefix(h1) + t*bc
    ps_kernel<<<16, 256>>>();
    sgemm_tn<<<dim3(C_ / BN, (S_ * B_) / BM), 256>>>(pPS, H_, Wc, H_, bc, traj, H_, C_, 2);
    // logits = Hr @ Wr^T + bout  (tf32 mma.sync 128x256), scatter to [B,S,V]
    mma_logits<<<dim3((S_ * B_) / 128, V_ / 256), 256, mma_smem>>>(pHr, pWr, bout, out);
}

// round 16
// speedup vs baseline: 2.1851x; 1.0427x over previous
#include <cuda_runtime.h>
#include <cstdint>

#define B_ 4
#define S_ 1024
#define E_ 512
#define C_ 256
#define H_ 1024
#define V_ 32000
#define GR 128    // CTAs in persistent recurrence (co-resident, 1/SM)

typedef unsigned long long ull;

// ---------------- scratch device globals ----------------
__device__ float g_X [S_ * B_ * E_];    // embeddings [r=t*4+b][E]
__device__ float g_Z [S_ * B_ * H_];    // X@W0x^T + b0
__device__ float g_H1[S_ * B_ * H_];    // exact h1 [r][H]   (traj prefix)
__device__ float g_Hr[S_ * B_ * H_];    // tf32-rounded h1   (GEMM A operand)
__device__ float g_PS[S_ * B_ * H_];    // exclusive prefix sums of h1
__device__ float g_Wr[(size_t)V_ * H_]; // tf32-rounded Wout
__device__ float g_M [H_ * H_];         // W0c @ Wc
__device__ float g_v [H_];              // W0c @ bc
__device__ float g_u  [H_ * B_];        // u state [k][b]
__device__ float g_h1s[H_ * B_];        // current h1 [k][b]
__device__ unsigned g_ctr;

__device__ __forceinline__ uint32_t f2tf(float f)
{
    uint32_t r;
    asm("cvt.rna.tf32.f32 %0, %1;" : "=r"(r) : "f"(f));
    return r;
}

// ---- packed f32x2 helpers (base sm_100+ PTX, not an 'a' feature) ----
__device__ __forceinline__ ull pk2(float lo, float hi)
{
    ull o;
    asm("mov.b64 %0, {%1, %2};" : "=l"(o) : "r"(__float_as_uint(lo)), "r"(__float_as_uint(hi)));
    return o;
}
__device__ __forceinline__ ull add2(ull a, ull b)
{
    ull o;
    asm("add.rn.f32x2 %0, %1, %2;" : "=l"(o) : "l"(a), "l"(b));
    return o;
}
__device__ __forceinline__ void fma2(ull& d, ull a, ull b)
{
    asm("fma.rn.f32x2 %0, %1, %2, %0;" : "+l"(d) : "l"(a), "l"(b));
}

__global__ void reset_kernel()
{
    int i = blockIdx.x * blockDim.x + threadIdx.x;
    if (i < H_ * B_) g_u[i] = 0.f;
    if (i == 0) g_ctr = 0u;
}

// ---------------- embedding ----------------
__global__ void embed_kernel(const int* __restrict__ ids,
                             const float* __restrict__ tok,
                             const float* __restrict__ pos)
{
    int r = blockIdx.x;            // r = t*4 + b
    int t = r >> 2, b = r & 3;
    int id = ids[b * S_ + t];
    const float4* tp = (const float4*)(tok + (size_t)id * E_);
    const float4* pp = (const float4*)(pos + (size_t)t * E_);
    float4* xp = (float4*)(g_X + (size_t)r * E_);
    int e = threadIdx.x;
    float4 a = tp[e], p = pp[e];
    xp[e] = make_float4(a.x + p.x, a.y + p.y, a.z + p.z, a.w + p.w);
}

// ---------------- M = W0c @ Wc  and  v = W0c @ bc ----------------
__global__ void mcomp_kernel(const float* __restrict__ W0,
                             const float* __restrict__ Wc)
{
    int j = blockIdx.x * 256 + threadIdx.x;   // 0..1023
    int i = blockIdx.y;                       // 0..1023
    const float* w0r = W0 + (size_t)i * (E_ + C_) + E_;
    float acc = 0.f;
#pragma unroll 4
    for (int c = 0; c < C_; c++)
        acc += w0r[c] * Wc[(size_t)c * H_ + j];
    g_M[(size_t)i * H_ + j] = acc;
}

__global__ void vcomp_kernel(const float* __restrict__ W0,
                             const float* __restrict__ bc)
{
    int i = blockIdx.x * 256 + threadIdx.x;
    if (i >= H_) return;
    const float* w0r = W0 + (size_t)i * (E_ + C_) + E_;
    float acc = 0.f;
#pragma unroll 4
    for (int c = 0; c < C_; c++) acc += w0r[c] * bc[c];
    g_v[i] = acc;
}

// ---------------- round Wout to tf32 (rna) ----------------
__global__ void roundw_kernel(const float* __restrict__ src, int n4)
{
    int i = blockIdx.x * blockDim.x + threadIdx.x;
    int stride = gridDim.x * blockDim.x;
    for (; i < n4; i += stride) {
        float4 vv = ((const float4*)src)[i];
        uint4 o = make_uint4(f2tf(vv.x), f2tf(vv.y), f2tf(vv.z), f2tf(vv.w));
        ((uint4*)g_Wr)[i] = o;
    }
}

// ---------------- fp32 SGEMM: C = A[M,K] @ Bw[N,K]^T + bias ----------------
#define BM 128
#define BN 128
#define BK 16
#define PADW 132

__global__ __launch_bounds__(256, 2) void sgemm_tn(
    const float* __restrict__ A, int lda,
    const float* __restrict__ Bw, int ldb,
    const float* __restrict__ bias,
    float* __restrict__ Cout,
    int K, int Nout, int mode)
{
    __shared__ float As[BK][PADW];
    __shared__ float Bs[BK][PADW];

    int tid = threadIdx.x;
    int tx = tid & 15, ty = tid >> 4;
    int bm = blockIdx.y * BM, bn = blockIdx.x * BN;

    float acc[8][8];
#pragma unroll
    for (int i = 0; i < 8; i++)
#pragma unroll
        for (int j = 0; j < 8; j++) acc[i][j] = 0.f;

    int lrow = tid >> 2;
    int lkq  = (tid & 3) * 4;

    for (int kt = 0; kt < K; kt += BK) {
#pragma unroll
        for (int h = 0; h < 2; h++) {
            int row = lrow + h * 64;
            float4 va = *(const float4*)(A  + (size_t)(bm + row) * lda + kt + lkq);
            As[lkq + 0][row] = va.x; As[lkq + 1][row] = va.y;
            As[lkq + 2][row] = va.z; As[lkq + 3][row] = va.w;
            float4 vb = *(const float4*)(Bw + (size_t)(bn + row) * ldb + kt + lkq);
            Bs[lkq + 0][row] = vb.x; Bs[lkq + 1][row] = vb.y;
            Bs[lkq + 2][row] = vb.z; Bs[lkq + 3][row] = vb.w;
        }
        __syncthreads();
#pragma unroll
        for (int kk = 0; kk < BK; kk++) {
            float a[8], b[8];
            *(float4*)(a)     = *(const float4*)&As[kk][ty * 8];
            *(float4*)(a + 4) = *(const float4*)&As[kk][ty * 8 + 4];
            *(float4*)(b)     = *(const float4*)&Bs[kk][tx * 8];
            *(float4*)(b + 4) = *(const float4*)&Bs[kk][tx * 8 + 4];
#pragma unroll
            for (int i = 0; i < 8; i++)
#pragma unroll
                for (int j = 0; j < 8; j++)
                    acc[i][j] += a[i] * b[j];
        }
        __syncthreads();
    }

    float bv[8];
#pragma unroll
    for (int j = 0; j < 8; j++) bv[j] = bias[bn + tx * 8 + j];

#pragma unroll
    for (int i = 0; i < 8; i++) {
        int m = bm + ty * 8 + i;
        size_t base;
        float bsc = 1.f;
        if (mode == 2) {
            int bb = m & 3, tt = m >> 2;
            base = ((size_t)bb * S_ + tt) * (size_t)Nout;
            bsc = (float)tt;
        } else {
            base = (size_t)m * (size_t)Nout;
        }
        float4 o0, o1;
        o0.x = acc[i][0] + bv[0] * bsc; o0.y = acc[i][1] + bv[1] * bsc;
        o0.z = acc[i][2] + bv[2] * bsc; o0.w = acc[i][3] + bv[3] * bsc;
        o1.x = acc[i][4] + bv[4] * bsc; o1.y = acc[i][5] + bv[5] * bsc;
        o1.z = acc[i][6] + bv[6] * bsc; o1.w = acc[i][7] + bv[7] * bsc;
        *(float4*)(Cout + base + bn + tx * 8)     = o0;
        *(float4*)(Cout + base + bn + tx * 8 + 4) = o1;
    }
}

// ---------------- global barrier ----------------
// tid0's __threadfence() (fence.gpu) + release/acquire pair make post-poll
// global reads observe remote CTAs' writes. Do not weaken.
__device__ __forceinline__ void gbar(unsigned target)
{
    __syncthreads();
    if (threadIdx.x == 0) {
        __threadfence();
        asm volatile("red.release.gpu.add.u32 [%0], %1;" :: "l"(&g_ctr), "r"(1u) : "memory");
        unsigned v;
        do {
            asm volatile("ld.acquire.gpu.u32 %0, [%1];" : "=r"(v) : "l"(&g_ctr) : "memory");
        } while (v < target);
    }
    __syncthreads();
}

// reduce 16 packed f32x2 across 32 lanes; lane l ends with packed value idx (l>>1).
// Per-scalar addition tree is identical to the scalar red32 (own + received,
// folding lane bits 16,8,4,2,1 in order) -> results bitwise match R14.
__device__ __forceinline__ ull red16p(const ull* v, int lane)
{
    ull a[8];
#pragma unroll
    for (int i = 0; i < 8; i++) {
        ull s = (lane & 16) ? v[i] : v[i + 8];
        ull r = __shfl_xor_sync(0xffffffffu, s, 16);
        a[i] = add2((lane & 16) ? v[i + 8] : v[i], r);
    }
    ull b[4];
#pragma unroll
    for (int i = 0; i < 4; i++) {
        ull s = (lane & 8) ? a[i] : a[i + 4];
        ull r = __shfl_xor_sync(0xffffffffu, s, 8);
        b[i] = add2((lane & 8) ? a[i + 4] : a[i], r);
    }
    ull c2[2];
#pragma unroll
    for (int i = 0; i < 2; i++) {
        ull s = (lane & 4) ? b[i] : b[i + 2];
        ull r = __shfl_xor_sync(0xffffffffu, s, 4);
        c2[i] = add2((lane & 4) ? b[i + 2] : b[i], r);
    }
    ull d;
    {
        ull s = (lane & 2) ? c2[0] : c2[1];
        ull r = __shfl_xor_sync(0xffffffffu, s, 2);
        d = add2((lane & 2) ? c2[1] : c2[0], r);
    }
    ull r = __shfl_xor_sync(0xffffffffu, d, 1);
    return add2(d, r);
}

// ---------------- persistent u-space recurrence, K-split, packed f32x2 ----------------
// 128 CTAs x 256 threads. CTA c owns h-rows [8c, 8c+8).
// Warp w owns k-slice [128w,128w+128); lane l owns k-quad kq = 128w + 4l.
// Weights (W1, M row-slices over own k-quad) live in registers (scalar; packed on the fly).
__global__ __launch_bounds__(256, 1) void recur3(
    const float* __restrict__ W1, const float* __restrict__ b1)
{
    __shared__ float sred[256];        // 8 warps x 32 scalar partials

    int c = blockIdx.x, tid = threadIdx.x;
    int w = tid >> 5, lane = tid & 31;
    int rowbase = c * 8;
    int kq = w * 128 + lane * 4;

    float w1a[8][4], ma[8][4];
#pragma unroll
    for (int row = 0; row < 8; row++) {
        float4 wv = *(const float4*)(W1 + (size_t)(rowbase + row) * H_ + kq);
        w1a[row][0] = wv.x; w1a[row][1] = wv.y; w1a[row][2] = wv.z; w1a[row][3] = wv.w;
        float4 mv = *(const float4*)(g_M + (size_t)(rowbase + row) * H_ + kq);
        ma[row][0] = mv.x; ma[row][1] = mv.y; ma[row][2] = mv.z; ma[row][3] = mv.w;
    }
    int fr = rowbase + ((tid & 31) >> 2);
    float rb1 = b1[fr];
    float rv  = g_v[fr];
    float myu = 0.f;

    float4 zpre[4];
#pragma unroll
    for (int b = 0; b < 4; b++)
        zpre[b] = *(const float4*)(g_Z + (size_t)b * H_ + kq);

    unsigned bar = 0;
    for (int t = 0; t < S_; t++) {
        int t4 = t * 4;

        // ---- h0 for own k-quad, packed per batch-pair: h0p[i][j] = (h0[i][2j], h0[i][2j+1]) ----
        float zf[4][4];                // [b][i]
#pragma unroll
        for (int b = 0; b < 4; b++)
            *(float4*)&zf[b][0] = zpre[b];
        ull h0p[4][2];
#pragma unroll
        for (int i = 0; i < 4; i++) {
            float4 uv = *(const float4*)(g_u + (kq + i) * 4);
            h0p[i][0] = pk2(fmaxf(zf[0][i] + uv.x, 0.f), fmaxf(zf[1][i] + uv.y, 0.f));
            h0p[i][1] = pk2(fmaxf(zf[2][i] + uv.z, 0.f), fmaxf(zf[3][i] + uv.w, 0.f));
        }

        // ---- phase A partials: pacc[row*2+j] packed over own 4 k's ----
        {
            ull pacc[16];
#pragma unroll
            for (int p = 0; p < 16; p++) pacc[p] = 0ULL;
#pragma unroll
            for (int row = 0; row < 8; row++)
#pragma unroll
                for (int i = 0; i < 4; i++) {
                    ull pw = pk2(w1a[row][i], w1a[row][i]);
                    fma2(pacc[row * 2 + 0], pw, h0p[i][0]);
                    fma2(pacc[row * 2 + 1], pw, h0p[i][1]);
                }
            ull red = red16p(pacc, lane);
            if ((lane & 1) == 0)
                *(ull*)&sred[w * 32 + lane] = red;   // floats [2p], [2p+1]
        }
        __syncthreads();
        if (tid < 32) {
            float tot = 0.f;
#pragma unroll
            for (int w2 = 0; w2 < 8; w2++) tot += sred[w2 * 32 + tid];
            float h = fmaxf(tot + rb1, 0.f);
            int b = tid & 3;
            g_h1s[fr * 4 + b] = h;
            g_H1[(size_t)(t4 + b) * H_ + fr] = h;
            g_Hr[(size_t)(t4 + b) * H_ + fr] = __uint_as_float(f2tf(h));
        }
        gbar(++bar * GR);

        // ---- phase B: read h1 slice (packed), partials with M ----
        {
            ull hp[4][2];
#pragma unroll
            for (int i = 0; i < 4; i++) {
                float4 hv = *(const float4*)(g_h1s + (kq + i) * 4);
                hp[i][0] = pk2(hv.x, hv.y);
                hp[i][1] = pk2(hv.z, hv.w);
            }
            ull pacc[16];
#pragma unroll
            for (int p = 0; p < 16; p++) pacc[p] = 0ULL;
#pragma unroll
            for (int row = 0; row < 8; row++)
#pragma unroll
                for (int i = 0; i < 4; i++) {
                    ull pw = pk2(ma[row][i], ma[row][i]);
                    fma2(pacc[row * 2 + 0], pw, hp[i][0]);
                    fma2(pacc[row * 2 + 1], pw, hp[i][1]);
                }
            ull red = red16p(pacc, lane);
            if ((lane & 1) == 0)
                *(ull*)&sred[w * 32 + lane] = red;
        }

        // prefetch next step's Z (hides L2 latency under the coming barrier)
        {
            int tn4 = (t + 1 < S_ ? t + 1 : t) * 4;
#pragma unroll
            for (int b = 0; b < 4; b++)
                zpre[b] = *(const float4*)(g_Z + (size_t)(tn4 + b) * H_ + kq);
        }

        __syncthreads();
        if (tid < 32) {
            float tot = 0.f;
#pragma unroll
            for (int w2 = 0; w2 < 8; w2++) tot += sred[w2 * 32 + tid];
            myu += tot + rv;
            g_u[fr * 4 + (tid & 3)] = myu;
        }
        gbar(++bar * GR);
    }
}

// ---------------- exclusive prefix sums of h1 over t ----------------
__global__ void ps_kernel()
{
    int idx = blockIdx.x * 256 + threadIdx.x;  // 0..4095
    int k = idx & 1023, b = idx >> 10;
    float acc = 0.f;
    for (int t = 0; t < S_; t += 4) {
        float x0 = g_H1[(size_t)((t + 0) * 4 + b) * H_ + k];
        float x1 = g_H1[(size_t)((t + 1) * 4 + b) * H_ + k];
        float x2 = g_H1[(size_t)((t + 2) * 4 + b) * H_ + k];
        float x3 = g_H1[(size_t)((t + 3) * 4 + b) * H_ + k];
        g_PS[(size_t)((t + 0) * 4 + b) * H_ + k] = acc; acc += x0;
        g_PS[(size_t)((t + 1) * 4 + b) * H_ + k] = acc; acc += x1;
        g_PS[(size_t)((t + 2) * 4 + b) * H_ + k] = acc; acc += x2;
        g_PS[(size_t)((t + 3) * 4 + b) * H_ + k] = acc; acc += x3;
    }
}

// ======== tf32 mma.sync logits GEMM: 128x256 tile, 8 warps of 64x64, BK=32 ========
#define TKS 36                         // 32 + 4 pad; banks (4g+tq+c)%32: conflict-free
#define A_W (128 * TKS)                // 4608 words
#define B_W (256 * TKS)                // 9216 words
#define STW (A_W + B_W)                // 13824 words = 55296 B
#define NST 3                          // 165888 B total

__device__ __forceinline__ void cpa16(uint32_t dst, const float* src)
{
    asm volatile("cp.async.cg.shared.global [%0], [%1], 16;" :: "r"(dst), "l"(src));
}

static __device__ __forceinline__ uint32_t smem_u32(const void* p)
{
    uint32_t a;
    asm("{ .reg .u64 t; cvta.to.shared.u64 t, %1; cvt.u32.u64 %0, t; }" : "=r"(a) : "l"(p));
    return a;
}

__global__ __launch_bounds__(256, 1) void mma_logits(
    const float* __restrict__ A,    // g_Hr [4096][1024]
    const float* __restrict__ Bw,   // g_Wr [32000][1024]
    const float* __restrict__ bias,
    float* __restrict__ Cout)
{
    extern __shared__ float sm[];
    int tid = threadIdx.x;
    int lane = tid & 31, wid = tid >> 5;
    int wm = (wid & 1) * 64;
    int wn = (wid >> 1) * 64;
    int g  = lane >> 2, tq = lane & 3;

    int bm = blockIdx.x * 128;
    int bn = blockIdx.y * 256;

    const float* Arow = A  + (size_t)bm * H_;
    const float* Brow = Bw + (size_t)bn * H_;

    float c[4][8][4];
#pragma unroll
    for (int mt = 0; mt < 4; mt++)
#pragma unroll
        for (int nt = 0; nt < 8; nt++)
#pragma unroll
            for (int i = 0; i < 4; i++) c[mt][nt][i] = 0.f;

    // loader: A 128 rows x 8 items + B 256 rows x 8 items (16B each) = 3072 items
    auto load_stage = [&](int st, int koff) {
        float* As = sm + st * STW;
        float* Bs = As + A_W;
#pragma unroll
        for (int j = 0; j < 12; j++) {
            int item = tid + j * 256;
            if (item < 1024) {
                int r = item >> 3, q = (item & 7) * 4;
                cpa16(smem_u32(&As[r * TKS + q]), Arow + (size_t)r * H_ + koff + q);
            } else {
                int it = item - 1024;
                int r = it >> 3, q = (it & 7) * 4;
                cpa16(smem_u32(&Bs[r * TKS + q]), Brow + (size_t)r * H_ + koff + q);
            }
        }
        asm volatile("cp.async.commit_group;" ::: "memory");
    };

    load_stage(0, 0);
    load_stage(1, 32);

    for (int cc = 0; cc < 32; cc++) {
        asm volatile("cp.async.wait_group 1;" ::: "memory");
        __syncthreads();

        if (cc + 2 < 32) load_stage((cc + 2) % NST, (cc + 2) * 32);

        const float* As = sm + (cc % NST) * STW;
        const float* Bs = As + A_W;

#pragma unroll
        for (int ks = 0; ks < 4; ks++) {
            int kb = ks * 8;
            uint32_t a[4][4];
#pragma unroll
            for (int mt = 0; mt < 4; mt++) {
                int m = wm + mt * 16 + g;
                a[mt][0] = __float_as_uint(As[m * TKS + kb + tq]);
                a[mt][1] = __float_as_uint(As[(m + 8) * TKS + kb + tq]);
                a[mt][2] = __float_as_uint(As[m * TKS + kb + tq + 4]);
                a[mt][3] = __float_as_uint(As[(m + 8) * TKS + kb + tq + 4]);
            }
            uint32_t b[8][2];
#pragma unroll
            for (int nt = 0; nt < 8; nt++) {
                int n = wn + nt * 8 + g;
                b[nt][0] = __float_as_uint(Bs[n * TKS + kb + tq]);
                b[nt][1] = __float_as_uint(Bs[n * TKS + kb + tq + 4]);
            }
#pragma unroll
            for (int mt = 0; mt < 4; mt++)
#pragma unroll
                for (int nt = 0; nt < 8; nt++) {
                    asm volatile(
                        "mma.sync.aligned.m16n8k8.row.col.f32.tf32.tf32.f32 "
                        "{%0,%1,%2,%3}, {%4,%5,%6,%7}, {%8,%9}, {%0,%1,%2,%3};\n"
                        : "+f"(c[mt][nt][0]), "+f"(c[mt][nt][1]),
                          "+f"(c[mt][nt][2]), "+f"(c[mt][nt][3])
                        : "r"(a[mt][0]), "r"(a[mt][1]), "r"(a[mt][2]), "r"(a[mt][3]),
                          "r"(b[nt][0]), "r"(b[nt][1]));
                }
        }
        __syncthreads();
    }

#pragma unroll
    for (int nt = 0; nt < 8; nt++) {
        int col = bn + wn + nt * 8 + tq * 2;
        float bv0 = bias[col], bv1 = bias[col + 1];
#pragma unroll
        for (int mt = 0; mt < 4; mt++) {
            int m0 = bm + wm + mt * 16 + g;
            {
                int bb = m0 & 3, tt = m0 >> 2;
                float2 o = make_float2(c[mt][nt][0] + bv0, c[mt][nt][1] + bv1);
                *(float2*)(Cout + ((size_t)bb * S_ + tt) * (size_t)V_ + col) = o;
            }
            {
                int m1 = m0 + 8;
                int bb = m1 & 3, tt = m1 >> 2;
                float2 o = make_float2(c[mt][nt][2] + bv0, c[mt][nt][3] + bv1);
                *(float2*)(Cout + ((size_t)bb * S_ + tt) * (size_t)V_ + col) = o;
            }
        }
    }
}

// ---------------- launch ----------------
extern "C" void kernel_launch(void* const* d_in, const int* in_sizes, int n_in,
                              void* d_out, int out_size)
{
    const int*   ids  = (const int*)  d_in[0];
    const float* tok  = (const float*)d_in[1];
    const float* pos  = (const float*)d_in[2];
    const float* W0   = (const float*)d_in[3];
    const float* b0   = (const float*)d_in[4];
    const float* W1   = (const float*)d_in[5];
    const float* b1   = (const float*)d_in[6];
    const float* Wout = (const float*)d_in[7];
    const float* bout = (const float*)d_in[8];
    const float* Wc   = (const float*)d_in[9];
    const float* bc   = (const float*)d_in[10];

    float* out  = (float*)d_out;                         // logits [B,S,V]
    float* traj = out + (size_t)B_ * S_ * V_;            // traj   [B,S,C]

    float *pX, *pZ, *pPS, *pHr, *pWr;
    cudaGetSymbolAddress((void**)&pX,  g_X);
    cudaGetSymbolAddress((void**)&pZ,  g_Z);
    cudaGetSymbolAddress((void**)&pPS, g_PS);
    cudaGetSymbolAddress((void**)&pHr, g_Hr);
    cudaGetSymbolAddress((void**)&pWr, g_Wr);

    const int mma_smem = NST * STW * 4;                   // 165888 B
    cudaFuncSetAttribute(mma_logits, cudaFuncAttributeMaxDynamicSharedMemorySize, mma_smem);

    reset_kernel<<<16, 256>>>();
    embed_kernel<<<S_ * B_, 128>>>(ids, tok, pos);
    // Z = X @ W0x^T + b0   (M=4096, N=1024, K=512)
    sgemm_tn<<<dim3(H_ / BN, (S_ * B_) / BM), 256>>>(pX, E_, W0, E_ + C_, b0, pZ, E_, H_, 0);
    // precompute M = W0c@Wc, v = W0c@bc, round Wout to tf32
    mcomp_kernel<<<dim3(4, 1024), 256>>>(W0, Wc);
    vcomp_kernel<<<4, 256>>>(W0, bc);
    roundw_kernel<<<2048, 256>>>(Wout, V_ * H_ / 4);
    // sequential recurrence (u-space, K-split, packed f32x2)
    recur3<<<GR, 256>>>(W1, b1);
    // traj = Wc @ prefix(h1) + t*bc
    ps_kernel<<<16, 256>>>();
    sgemm_tn<<<dim3(C_ / BN, (S_ * B_) / BM), 256>>>(pPS, H_, Wc, H_, bc, traj, H_, C_, 2);
    // logits = Hr @ Wr^T + bout  (tf32 mma.sync 128x256, BK=32), scatter to [B,S,V]
    mma_logits<<<dim3((S_ * B_) / 128, V_ / 256), 256, mma_smem>>>(pHr, pWr, bout, out);
}

// round 17
// speedup vs baseline: 2.2061x; 1.0096x over previous
#include <cuda_runtime.h>
#include <cstdint>

#define B_ 4
#define S_ 1024
#define E_ 512
#define C_ 256
#define H_ 1024
#define V_ 32000
#define GR 128    // CTAs in persistent recurrence (co-resident, 1/SM)

typedef unsigned long long ull;

// ---------------- scratch device globals ----------------
__device__ float g_X [S_ * B_ * E_];    // embeddings [r=t*4+b][E]
__device__ float g_Z [S_ * B_ * H_];    // X@W0x^T + b0
__device__ float g_H1[S_ * B_ * H_];    // exact h1 [r][H]   (traj prefix)
__device__ float g_Hr[S_ * B_ * H_];    // tf32-rounded h1   (GEMM A operand)
__device__ float g_PS[S_ * B_ * H_];    // exclusive prefix sums of h1
__device__ float g_CS[32 * 4096];       // chunk sums for the 3-phase scan
__device__ float g_Wr[(size_t)V_ * H_]; // tf32-rounded Wout
__device__ float g_M [H_ * H_];         // W0c @ Wc
__device__ float g_v [H_];              // W0c @ bc
__device__ float g_u  [H_ * B_];        // u state [k][b]
__device__ float g_h1s[H_ * B_];        // current h1 [k][b]
__device__ unsigned g_ctr;

__device__ __forceinline__ uint32_t f2tf(float f)
{
    uint32_t r;
    asm("cvt.rna.tf32.f32 %0, %1;" : "=r"(r) : "f"(f));
    return r;
}

// ---- packed f32x2 helpers (base sm_100+ PTX, not an 'a' feature) ----
__device__ __forceinline__ ull pk2(float lo, float hi)
{
    ull o;
    asm("mov.b64 %0, {%1, %2};" : "=l"(o) : "r"(__float_as_uint(lo)), "r"(__float_as_uint(hi)));
    return o;
}
__device__ __forceinline__ ull add2(ull a, ull b)
{
    ull o;
    asm("add.rn.f32x2 %0, %1, %2;" : "=l"(o) : "l"(a), "l"(b));
    return o;
}
__device__ __forceinline__ void fma2(ull& d, ull a, ull b)
{
    asm("fma.rn.f32x2 %0, %1, %2, %0;" : "+l"(d) : "l"(a), "l"(b));
}

__global__ void reset_kernel()
{
    int i = blockIdx.x * blockDim.x + threadIdx.x;
    if (i < H_ * B_) g_u[i] = 0.f;
    if (i == 0) g_ctr = 0u;
}

// ---------------- embedding ----------------
__global__ void embed_kernel(const int* __restrict__ ids,
                             const float* __restrict__ tok,
                             const float* __restrict__ pos)
{
    int r = blockIdx.x;            // r = t*4 + b
    int t = r >> 2, b = r & 3;
    int id = ids[b * S_ + t];
    const float4* tp = (const float4*)(tok + (size_t)id * E_);
    const float4* pp = (const float4*)(pos + (size_t)t * E_);
    float4* xp = (float4*)(g_X + (size_t)r * E_);
    int e = threadIdx.x;
    float4 a = tp[e], p = pp[e];
    xp[e] = make_float4(a.x + p.x, a.y + p.y, a.z + p.z, a.w + p.w);
}

// ---------------- M = W0c @ Wc  and  v = W0c @ bc ----------------
__global__ void mcomp_kernel(const float* __restrict__ W0,
                             const float* __restrict__ Wc)
{
    int j = blockIdx.x * 256 + threadIdx.x;   // 0..1023
    int i = blockIdx.y;                       // 0..1023
    const float* w0r = W0 + (size_t)i * (E_ + C_) + E_;
    float acc = 0.f;
#pragma unroll 4
    for (int c = 0; c < C_; c++)
        acc += w0r[c] * Wc[(size_t)c * H_ + j];
    g_M[(size_t)i * H_ + j] = acc;
}

__global__ void vcomp_kernel(const float* __restrict__ W0,
                             const float* __restrict__ bc)
{
    int i = blockIdx.x * 256 + threadIdx.x;
    if (i >= H_) return;
    const float* w0r = W0 + (size_t)i * (E_ + C_) + E_;
    float acc = 0.f;
#pragma unroll 4
    for (int c = 0; c < C_; c++) acc += w0r[c] * bc[c];
    g_v[i] = acc;
}

// ---------------- round Wout to tf32 (rna) ----------------
__global__ void roundw_kernel(const float* __restrict__ src, int n4)
{
    int i = blockIdx.x * blockDim.x + threadIdx.x;
    int stride = gridDim.x * blockDim.x;
    for (; i < n4; i += stride) {
        float4 vv = ((const float4*)src)[i];
        uint4 o = make_uint4(f2tf(vv.x), f2tf(vv.y), f2tf(vv.z), f2tf(vv.w));
        ((uint4*)g_Wr)[i] = o;
    }
}

// ---------------- fp32 SGEMM: C = A[M,K] @ Bw[N,K]^T + bias ----------------
#define BM 128
#define BN 128
#define BK 16
#define PADW 132

__global__ __launch_bounds__(256, 2) void sgemm_tn(
    const float* __restrict__ A, int lda,
    const float* __restrict__ Bw, int ldb,
    const float* __restrict__ bias,
    float* __restrict__ Cout,
    int K, int Nout, int mode)
{
    __shared__ float As[BK][PADW];
    __shared__ float Bs[BK][PADW];

    int tid = threadIdx.x;
    int tx = tid & 15, ty = tid >> 4;
    int bm = blockIdx.y * BM, bn = blockIdx.x * BN;

    float acc[8][8];
#pragma unroll
    for (int i = 0; i < 8; i++)
#pragma unroll
        for (int j = 0; j < 8; j++) acc[i][j] = 0.f;

    int lrow = tid >> 2;
    int lkq  = (tid & 3) * 4;

    for (int kt = 0; kt < K; kt += BK) {
#pragma unroll
        for (int h = 0; h < 2; h++) {
            int row = lrow + h * 64;
            float4 va = *(const float4*)(A  + (size_t)(bm + row) * lda + kt + lkq);
            As[lkq + 0][row] = va.x; As[lkq + 1][row] = va.y;
            As[lkq + 2][row] = va.z; As[lkq + 3][row] = va.w;
            float4 vb = *(const float4*)(Bw + (size_t)(bn + row) * ldb + kt + lkq);
            Bs[lkq + 0][row] = vb.x; Bs[lkq + 1][row] = vb.y;
            Bs[lkq + 2][row] = vb.z; Bs[lkq + 3][row] = vb.w;
        }
        __syncthreads();
#pragma unroll
        for (int kk = 0; kk < BK; kk++) {
            float a[8], b[8];
            *(float4*)(a)     = *(const float4*)&As[kk][ty * 8];
            *(float4*)(a + 4) = *(const float4*)&As[kk][ty * 8 + 4];
            *(float4*)(b)     = *(const float4*)&Bs[kk][tx * 8];
            *(float4*)(b + 4) = *(const float4*)&Bs[kk][tx * 8 + 4];
#pragma unroll
            for (int i = 0; i < 8; i++)
#pragma unroll
                for (int j = 0; j < 8; j++)
                    acc[i][j] += a[i] * b[j];
        }
        __syncthreads();
    }

    float bv[8];
#pragma unroll
    for (int j = 0; j < 8; j++) bv[j] = bias[bn + tx * 8 + j];

#pragma unroll
    for (int i = 0; i < 8; i++) {
        int m = bm + ty * 8 + i;
        size_t base;
        float bsc = 1.f;
        if (mode == 2) {
            int bb = m & 3, tt = m >> 2;
            base = ((size_t)bb * S_ + tt) * (size_t)Nout;
            bsc = (float)tt;
        } else {
            base = (size_t)m * (size_t)Nout;
        }
        float4 o0, o1;
        o0.x = acc[i][0] + bv[0] * bsc; o0.y = acc[i][1] + bv[1] * bsc;
        o0.z = acc[i][2] + bv[2] * bsc; o0.w = acc[i][3] + bv[3] * bsc;
        o1.x = acc[i][4] + bv[4] * bsc; o1.y = acc[i][5] + bv[5] * bsc;
        o1.z = acc[i][6] + bv[6] * bsc; o1.w = acc[i][7] + bv[7] * bsc;
        *(float4*)(Cout + base + bn + tx * 8)     = o0;
        *(float4*)(Cout + base + bn + tx * 8 + 4) = o1;
    }
}

// ---------------- global barrier ----------------
// tid0's __threadfence() (fence.gpu) + release/acquire pair make post-poll
// global reads observe remote CTAs' writes. Do not weaken.
__device__ __forceinline__ void gbar(unsigned target)
{
    __syncthreads();
    if (threadIdx.x == 0) {
        __threadfence();
        asm volatile("red.release.gpu.add.u32 [%0], %1;" :: "l"(&g_ctr), "r"(1u) : "memory");
        unsigned v;
        do {
            asm volatile("ld.acquire.gpu.u32 %0, [%1];" : "=r"(v) : "l"(&g_ctr) : "memory");
        } while (v < target);
    }
    __syncthreads();
}

// reduce 16 packed f32x2 across 32 lanes; lane l ends with packed value idx (l>>1).
// Per-scalar addition tree identical to scalar red32 -> bitwise-stable results.
__device__ __forceinline__ ull red16p(const ull* v, int lane)
{
    ull a[8];
#pragma unroll
    for (int i = 0; i < 8; i++) {
        ull s = (lane & 16) ? v[i] : v[i + 8];
        ull r = __shfl_xor_sync(0xffffffffu, s, 16);
        a[i] = add2((lane & 16) ? v[i + 8] : v[i], r);
    }
    ull b[4];
#pragma unroll
    for (int i = 0; i < 4; i++) {
        ull s = (lane & 8) ? a[i] : a[i + 4];
        ull r = __shfl_xor_sync(0xffffffffu, s, 8);
        b[i] = add2((lane & 8) ? a[i + 4] : a[i], r);
    }
    ull c2[2];
#pragma unroll
    for (int i = 0; i < 2; i++) {
        ull s = (lane & 4) ? b[i] : b[i + 2];
        ull r = __shfl_xor_sync(0xffffffffu, s, 4);
        c2[i] = add2((lane & 4) ? b[i + 2] : b[i], r);
    }
    ull d;
    {
        ull s = (lane & 2) ? c2[0] : c2[1];
        ull r = __shfl_xor_sync(0xffffffffu, s, 2);
        d = add2((lane & 2) ? c2[1] : c2[0], r);
    }
    ull r = __shfl_xor_sync(0xffffffffu, d, 1);
    return add2(d, r);
}

// ---------------- persistent u-space recurrence, K-split, packed f32x2 ----------------
// 128 CTAs x 256 threads. CTA c owns h-rows [8c, 8c+8).
// Warp w owns k-slice [128w,128w+128); lane l owns k-quad kq = 128w + 4l.
// g_H1/g_Hr archive stores deferred past the phase-A barrier (off arrival path).
__global__ __launch_bounds__(256, 1) void recur3(
    const float* __restrict__ W1, const float* __restrict__ b1)
{
    __shared__ float sred[256];        // 8 warps x 32 scalar partials

    int c = blockIdx.x, tid = threadIdx.x;
    int w = tid >> 5, lane = tid & 31;
    int rowbase = c * 8;
    int kq = w * 128 + lane * 4;

    float w1a[8][4], ma[8][4];
#pragma unroll
    for (int row = 0; row < 8; row++) {
        float4 wv = *(const float4*)(W1 + (size_t)(rowbase + row) * H_ + kq);
        w1a[row][0] = wv.x; w1a[row][1] = wv.y; w1a[row][2] = wv.z; w1a[row][3] = wv.w;
        float4 mv = *(const float4*)(g_M + (size_t)(rowbase + row) * H_ + kq);
        ma[row][0] = mv.x; ma[row][1] = mv.y; ma[row][2] = mv.z; ma[row][3] = mv.w;
    }
    int fr = rowbase + ((tid & 31) >> 2);
    float rb1 = b1[fr];
    float rv  = g_v[fr];
    float myu = 0.f;
    float hA  = 0.f;                   // carried h1 value for deferred archive stores

    float4 zpre[4];
#pragma unroll
    for (int b = 0; b < 4; b++)
        zpre[b] = *(const float4*)(g_Z + (size_t)b * H_ + kq);

    unsigned bar = 0;
    for (int t = 0; t < S_; t++) {
        int t4 = t * 4;

        // ---- h0 for own k-quad, packed per batch-pair ----
        float zf[4][4];                // [b][i]
#pragma unroll
        for (int b = 0; b < 4; b++)
            *(float4*)&zf[b][0] = zpre[b];
        ull h0p[4][2];
#pragma unroll
        for (int i = 0; i < 4; i++) {
            float4 uv = *(const float4*)(g_u + (kq + i) * 4);
            h0p[i][0] = pk2(fmaxf(zf[0][i] + uv.x, 0.f), fmaxf(zf[1][i] + uv.y, 0.f));
            h0p[i][1] = pk2(fmaxf(zf[2][i] + uv.z, 0.f), fmaxf(zf[3][i] + uv.w, 0.f));
        }

        // ---- phase A partials ----
        {
            ull pacc[16];
#pragma unroll
            for (int p = 0; p < 16; p++) pacc[p] = 0ULL;
#pragma unroll
            for (int row = 0; row < 8; row++)
#pragma unroll
                for (int i = 0; i < 4; i++) {
                    ull pw = pk2(w1a[row][i], w1a[row][i]);
                    fma2(pacc[row * 2 + 0], pw, h0p[i][0]);
                    fma2(pacc[row * 2 + 1], pw, h0p[i][1]);
                }
            ull red = red16p(pacc, lane);
            if ((lane & 1) == 0)
                *(ull*)&sred[w * 32 + lane] = red;
        }
        __syncthreads();
        if (tid < 32) {
            float tot = 0.f;
#pragma unroll
            for (int w2 = 0; w2 < 8; w2++) tot += sred[w2 * 32 + tid];
            float h = fmaxf(tot + rb1, 0.f);
            g_h1s[fr * 4 + (tid & 3)] = h;   // the only store peers need pre-barrier
            hA = h;
        }
        gbar(++bar * GR);

        // deferred archive stores (overlap phase B; consumed only post-kernel)
        if (tid < 32) {
            int b = tid & 3;
            g_H1[(size_t)(t4 + b) * H_ + fr] = hA;
            g_Hr[(size_t)(t4 + b) * H_ + fr] = __uint_as_float(f2tf(hA));
        }

        // ---- phase B: read h1 slice (packed), partials with M ----
        {
            ull hp[4][2];
#pragma unroll
            for (int i = 0; i < 4; i++) {
                float4 hv = *(const float4*)(g_h1s + (kq + i) * 4);
                hp[i][0] = pk2(hv.x, hv.y);
                hp[i][1] = pk2(hv.z, hv.w);
            }
            ull pacc[16];
#pragma unroll
            for (int p = 0; p < 16; p++) pacc[p] = 0ULL;
#pragma unroll
            for (int row = 0; row < 8; row++)
#pragma unroll
                for (int i = 0; i < 4; i++) {
                    ull pw = pk2(ma[row][i], ma[row][i]);
                    fma2(pacc[row * 2 + 0], pw, hp[i][0]);
                    fma2(pacc[row * 2 + 1], pw, hp[i][1]);
                }
            ull red = red16p(pacc, lane);
            if ((lane & 1) == 0)
                *(ull*)&sred[w * 32 + lane] = red;
        }

        // prefetch next step's Z (hides L2 latency under the coming barrier)
        {
            int tn4 = (t + 1 < S_ ? t + 1 : t) * 4;
#pragma unroll
            for (int b = 0; b < 4; b++)
                zpre[b] = *(const float4*)(g_Z + (size_t)(tn4 + b) * H_ + kq);
        }

        __syncthreads();
        if (tid < 32) {
            float tot = 0.f;
#pragma unroll
            for (int w2 = 0; w2 < 8; w2++) tot += sred[w2 * 32 + tid];
            myu += tot + rv;
            g_u[fr * 4 + (tid & 3)] = myu;
        }
        gbar(++bar * GR);
    }
}

// ---------------- 3-phase exclusive prefix sums of h1 over t ----------------
// chunk = 32 t's, 32 chunks. idx = b*1024 + k (4096 lanes).
__global__ void ps_a_kernel()
{
    int gidx = blockIdx.x * 256 + threadIdx.x;   // 0..131071
    int idx = gidx & 4095, chunk = gidx >> 12;
    int k = idx & 1023, b = idx >> 10;
    int t0 = chunk * 32;
    float s = 0.f;
    for (int t = t0; t < t0 + 32; t++)
        s += g_H1[(size_t)(t * 4 + b) * H_ + k];
    g_CS[chunk * 4096 + idx] = s;
}

__global__ void ps_b_kernel()
{
    int idx = blockIdx.x * 256 + threadIdx.x;    // 0..4095
    float acc = 0.f;
#pragma unroll
    for (int c2 = 0; c2 < 32; c2++) {
        float v = g_CS[c2 * 4096 + idx];
        g_CS[c2 * 4096 + idx] = acc;
        acc += v;
    }
}

__global__ void ps_c_kernel()
{
    int gidx = blockIdx.x * 256 + threadIdx.x;
    int idx = gidx & 4095, chunk = gidx >> 12;
    int k = idx & 1023, b = idx >> 10;
    int t0 = chunk * 32;
    float acc = g_CS[chunk * 4096 + idx];
    for (int t = t0; t < t0 + 32; t++) {
        size_t off = (size_t)(t * 4 + b) * H_ + k;
        g_PS[off] = acc;
        acc += g_H1[off];
    }
}

// ======== tf32 mma.sync logits GEMM: 128x256 tile, 8 warps of 64x64, BK=32, 4-stage ========
#define TKS 36                         // 32 + 4 pad; banks (4g+tq+c)%32: conflict-free
#define A_W (128 * TKS)                // 4608 words
#define B_W (256 * TKS)                // 9216 words
#define STW (A_W + B_W)                // 13824 words = 55296 B
#define NST 4                          // 221184 B total (fits 227 KB opt-in)

__device__ __forceinline__ void cpa16(uint32_t dst, const float* src)
{
    asm volatile("cp.async.cg.shared.global [%0], [%1], 16;" :: "r"(dst), "l"(src));
}

static __device__ __forceinline__ uint32_t smem_u32(const void* p)
{
    uint32_t a;
    asm("{ .reg .u64 t; cvta.to.shared.u64 t, %1; cvt.u32.u64 %0, t; }" : "=r"(a) : "l"(p));
    return a;
}

__global__ __launch_bounds__(256, 1) void mma_logits(
    const float* __restrict__ A,    // g_Hr [4096][1024]
    const float* __restrict__ Bw,   // g_Wr [32000][1024]
    const float* __restrict__ bias,
    float* __restrict__ Cout)
{
    extern __shared__ float sm[];
    int tid = threadIdx.x;
    int lane = tid & 31, wid = tid >> 5;
    int wm = (wid & 1) * 64;
    int wn = (wid >> 1) * 64;
    int g  = lane >> 2, tq = lane & 3;

    int bm = blockIdx.x * 128;
    int bn = blockIdx.y * 256;

    const float* Arow = A  + (size_t)bm * H_;
    const float* Brow = Bw + (size_t)bn * H_;

    float c[4][8][4];
#pragma unroll
    for (int mt = 0; mt < 4; mt++)
#pragma unroll
        for (int nt = 0; nt < 8; nt++)
#pragma unroll
            for (int i = 0; i < 4; i++) c[mt][nt][i] = 0.f;

    auto load_stage = [&](int st, int koff) {
        float* As = sm + st * STW;
        float* Bs = As + A_W;
#pragma unroll
        for (int j = 0; j < 12; j++) {
            int item = tid + j * 256;
            if (item < 1024) {
                int r = item >> 3, q = (item & 7) * 4;
                cpa16(smem_u32(&As[r * TKS + q]), Arow + (size_t)r * H_ + koff + q);
            } else {
                int it = item - 1024;
                int r = it >> 3, q = (it & 7) * 4;
                cpa16(smem_u32(&Bs[r * TKS + q]), Brow + (size_t)r * H_ + koff + q);
            }
        }
        asm volatile("cp.async.commit_group;" ::: "memory");
    };

    load_stage(0, 0);
    load_stage(1, 32);
    load_stage(2, 64);

    for (int cc = 0; cc < 32; cc++) {
        asm volatile("cp.async.wait_group 2;" ::: "memory");
        __syncthreads();

        if (cc + 3 < 32) load_stage((cc + 3) % NST, (cc + 3) * 32);

        const float* As = sm + (cc % NST) * STW;
        const float* Bs = As + A_W;

#pragma unroll
        for (int ks = 0; ks < 4; ks++) {
            int kb = ks * 8;
            uint32_t a[4][4];
#pragma unroll
            for (int mt = 0; mt < 4; mt++) {
                int m = wm + mt * 16 + g;
                a[mt][0] = __float_as_uint(As[m * TKS + kb + tq]);
                a[mt][1] = __float_as_uint(As[(m + 8) * TKS + kb + tq]);
                a[mt][2] = __float_as_uint(As[m * TKS + kb + tq + 4]);
                a[mt][3] = __float_as_uint(As[(m + 8) * TKS + kb + tq + 4]);
            }
            uint32_t b[8][2];
#pragma unroll
            for (int nt = 0; nt < 8; nt++) {
                int n = wn + nt * 8 + g;
                b[nt][0] = __float_as_uint(Bs[n * TKS + kb + tq]);
                b[nt][1] = __float_as_uint(Bs[n * TKS + kb + tq + 4]);
            }
#pragma unroll
            for (int mt = 0; mt < 4; mt++)
#pragma unroll
                for (int nt = 0; nt < 8; nt++) {
                    asm volatile(
                        "mma.sync.aligned.m16n8k8.row.col.f32.tf32.tf32.f32 "
                        "{%0,%1,%2,%3}, {%4,%5,%6,%7}, {%8,%9}, {%0,%1,%2,%3};\n"
                        : "+f"(c[mt][nt][0]), "+f"(c[mt][nt][1]),
                          "+f"(c[mt][nt][2]), "+f"(c[mt][nt][3])
                        : "r"(a[mt][0]), "r"(a[mt][1]), "r"(a[mt][2]), "r"(a[mt][3]),
                          "r"(b[nt][0]), "r"(b[nt][1]));
                }
        }
        __syncthreads();
    }

#pragma unroll
    for (int nt = 0; nt < 8; nt++) {
        int col = bn + wn + nt * 8 + tq * 2;
        float bv0 = bias[col], bv1 = bias[col + 1];
#pragma unroll
        for (int mt = 0; mt < 4; mt++) {
            int m0 = bm + wm + mt * 16 + g;
            {
                int bb = m0 & 3, tt = m0 >> 2;
                float2 o = make_float2(c[mt][nt][0] + bv0, c[mt][nt][1] + bv1);
                *(float2*)(Cout + ((size_t)bb * S_ + tt) * (size_t)V_ + col) = o;
            }
            {
                int m1 = m0 + 8;
                int bb = m1 & 3, tt = m1 >> 2;
                float2 o = make_float2(c[mt][nt][2] + bv0, c[mt][nt][3] + bv1);
                *(float2*)(Cout + ((size_t)bb * S_ + tt) * (size_t)V_ + col) = o;
            }
        }
    }
}

// ---------------- launch ----------------
extern "C" void kernel_launch(void* const* d_in, const int* in_sizes, int n_in,
                              void* d_out, int out_size)
{
    const int*   ids  = (const int*)  d_in[0];
    const float* tok  = (const float*)d_in[1];
    const float* pos  = (const float*)d_in[2];
    const float* W0   = (const float*)d_in[3];
    const float* b0   = (const float*)d_in[4];
    const float* W1   = (const float*)d_in[5];
    const float* b1   = (const float*)d_in[6];
    const float* Wout = (const float*)d_in[7];
    const float* bout = (const float*)d_in[8];
    const float* Wc   = (const float*)d_in[9];
    const float* bc   = (const float*)d_in[10];

    float* out  = (float*)d_out;                         // logits [B,S,V]
    float* traj = out + (size_t)B_ * S_ * V_;            // traj   [B,S,C]

    float *pX, *pZ, *pPS, *pHr, *pWr;
    cudaGetSymbolAddress((void**)&pX,  g_X);
    cudaGetSymbolAddress((void**)&pZ,  g_Z);
    cudaGetSymbolAddress((void**)&pPS, g_PS);
    cudaGetSymbolAddress((void**)&pHr, g_Hr);
    cudaGetSymbolAddress((void**)&pWr, g_Wr);

    const int mma_smem = NST * STW * 4;                   // 221184 B
    cudaFuncSetAttribute(mma_logits, cudaFuncAttributeMaxDynamicSharedMemorySize, mma_smem);

    reset_kernel<<<16, 256>>>();
    embed_kernel<<<S_ * B_, 128>>>(ids, tok, pos);
    // Z = X @ W0x^T + b0   (M=4096, N=1024, K=512)
    sgemm_tn<<<dim3(H_ / BN, (S_ * B_) / BM), 256>>>(pX, E_, W0, E_ + C_, b0, pZ, E_, H_, 0);
    // precompute M = W0c@Wc, v = W0c@bc, round Wout to tf32
    mcomp_kernel<<<dim3(4, 1024), 256>>>(W0, Wc);
    vcomp_kernel<<<4, 256>>>(W0, bc);
    roundw_kernel<<<2048, 256>>>(Wout, V_ * H_ / 4);
    // sequential recurrence (u-space, K-split, packed f32x2)
    recur3<<<GR, 256>>>(W1, b1);
    // traj = Wc @ prefix(h1) + t*bc   (3-phase parallel scan)
    ps_a_kernel<<<512, 256>>>();
    ps_b_kernel<<<16, 256>>>();
    ps_c_kernel<<<512, 256>>>();
    sgemm_tn<<<dim3(C_ / BN, (S_ * B_) / BM), 256>>>(pPS, H_, Wc, H_, bc, traj, H_, C_, 2);
    // logits = Hr @ Wr^T + bout  (tf32 mma.sync 128x256, BK=32, 4-stage), scatter to [B,S,V]
    mma_logits<<<dim3((S_ * B_) / 128, V_ / 256), 256, mma_smem>>>(pHr, pWr, bout, out);
}